// round 8
// baseline (speedup 1.0000x reference)
#include <cuda_runtime.h>
#include <cuda_bf16.h>
#include <math.h>

#define BB 4
#define NN 50000
#define BN 200000          // BB*NN
#define EE 600000
#define DD 128
#define DE 64
#define NPB 32             // nodes per epilogue block
#define SCAN_B 512
#define SCAN_NBLK ((BN + SCAN_B - 1) / SCAN_B)   // 391

// ---- scratch: static __device__ arrays only ----
__device__ float4 g_y4[(size_t)BN * 32];   // Σ alpha * x[dst]  per src (102.4 MB)
__device__ float4 g_u4[(size_t)BN * 16];   // Σ alpha * e_emb   per src (51.2 MB)
__device__ float  g_asum[BN];              // Σ alpha           per src
__device__ float  g_attsum[BN];            // Σ exp(logit)      per dst
__device__ float  g_attexp[EE];
__device__ float  g_qa[BN];
__device__ float  g_ka[BN];
__device__ float4 g_wqa4[32];
__device__ float4 g_wka4[32];
__device__ float4 g_wea4[16];
__device__ float  g_cb[1];
// CSR build
__device__ unsigned g_cnt[BN];             // degree histogram (by src)
__device__ unsigned g_off[BN];             // exclusive offsets
__device__ unsigned g_cur[BN];             // scatter cursors
__device__ uint2    g_offcnt[BN];          // packed {off, cnt} for gather
__device__ unsigned g_bsum[SCAN_NBLK];
__device__ unsigned g_boff[SCAN_NBLK];
__device__ int4     g_meta[EE];            // sorted-by-src: {gd, eid, alpha_bits, 0}

__device__ __forceinline__ void redg(float* p, float v) {
    unsigned long long gp = (unsigned long long)__cvta_generic_to_global(p);
    asm volatile("red.global.add.f32 [%0], %1;" :: "l"(gp), "f"(v) : "memory");
}
__device__ __forceinline__ void redgu(unsigned* p, unsigned v) {
    unsigned long long gp = (unsigned long long)__cvta_generic_to_global(p);
    asm volatile("red.global.add.u32 [%0], %1;" :: "l"(gp), "r"(v) : "memory");
}
__device__ __forceinline__ unsigned long long pk2(float x) {
    unsigned long long r;
    asm("mov.b64 %0, {%1, %1};" : "=l"(r) : "f"(x));
    return r;
}
__device__ __forceinline__ void ffma2(unsigned long long& d, unsigned long long a,
                                      unsigned long long b) {
    asm("fma.rn.f32x2 %0, %1, %2, %0;" : "+l"(d) : "l"(a), "l"(b));
}

// ---------------------------------------------------------------------------
__global__ void k_prep(const float* __restrict__ Wq, const float* __restrict__ Wk,
                       const float* __restrict__ Wew,
                       const float* __restrict__ bq, const float* __restrict__ bk,
                       const float* __restrict__ bew, const float* __restrict__ Wa) {
    int j = threadIdx.x;
    float aq = 0.f, ak = 0.f;
    for (int k = 0; k < DD; k++) {
        float wa = Wa[k];
        aq += Wq[j * DD + k] * wa;
        ak += Wk[j * DD + k] * wa;
    }
    ((float*)g_wqa4)[j] = aq;
    ((float*)g_wka4)[j] = ak;
    if (j < DE) {
        float ae = 0.f;
        for (int k = 0; k < DD; k++) ae += Wew[j * DD + k] * Wa[k];
        ((float*)g_wea4)[j] = ae;
    }
    if (j == 0) {
        float c = 0.f;
        for (int k = 0; k < DD; k++) c += (bq[k] + bk[k] + bew[k]) * Wa[k];
        g_cb[0] = c;
    }
}

// ---------------------------------------------------------------------------
// K1: per-node scalars + fused zeroing of attsum/cnt/cur
// ---------------------------------------------------------------------------
__global__ __launch_bounds__(256) void k_node(const float* __restrict__ x) {
    int lin = blockIdx.x * blockDim.x + threadIdx.x;
    if (lin < BN) { g_attsum[lin] = 0.f; g_cnt[lin] = 0u; g_cur[lin] = 0u; }
    int w = lin >> 5;
    int lane = threadIdx.x & 31;
    if (w >= BN) return;
    float4 xv = ((const float4*)x)[(size_t)w * 32 + lane];
    float4 wq = g_wqa4[lane];
    float4 wk = g_wka4[lane];
    float pq = xv.x * wq.x + xv.y * wq.y + xv.z * wq.z + xv.w * wq.w;
    float pk = xv.x * wk.x + xv.y * wk.y + xv.z * wk.z + xv.w * wk.w;
    #pragma unroll
    for (int o = 16; o > 0; o >>= 1) {
        pq += __shfl_xor_sync(0xffffffffu, pq, o);
        pk += __shfl_xor_sync(0xffffffffu, pk, o);
    }
    if (lane == 0) { g_qa[w] = pq; g_ka[w] = pk; }
}

// ---------------------------------------------------------------------------
// edge pass 1: logit/exp + attsum red + src-degree histogram
// ---------------------------------------------------------------------------
__global__ __launch_bounds__(128) void k_edge1(const int* __restrict__ ei,
                                               const int* __restrict__ bi,
                                               const float* __restrict__ e_emb) {
    int t = blockIdx.x * blockDim.x + threadIdx.x;
    int e = t >> 2;
    int sub = t & 3;
    if (e >= EE) return;
    const float4* er = (const float4*)(e_emb + (size_t)e * DE);
    float p = 0.f;
    #pragma unroll
    for (int i = 0; i < 4; i++) {
        float4 v  = er[sub * 4 + i];
        float4 wv = g_wea4[sub * 4 + i];
        p += v.x * wv.x + v.y * wv.y + v.z * wv.z + v.w * wv.w;
    }
    p += __shfl_xor_sync(0xffffffffu, p, 1);
    p += __shfl_xor_sync(0xffffffffu, p, 2);
    if (sub == 0) {
        int s = ei[e];
        int d = ei[EE + e];
        int b = bi[e];
        int gs = b * NN + s;
        int gd = b * NN + d;
        float logit = (g_qa[gs] + g_ka[gd] + p + g_cb[0]) * 0.25f;
        float ex = expf(logit);
        g_attexp[e] = ex;
        redg(&g_attsum[gd], ex);
        redgu(&g_cnt[gs], 1u);
    }
}

// ---------------------------------------------------------------------------
// 3-kernel exclusive scan of g_cnt -> g_off (+ packed offcnt)
// ---------------------------------------------------------------------------
__global__ void k_scanA() {
    __shared__ unsigned sh[SCAN_B];
    int i = blockIdx.x * SCAN_B + threadIdx.x;
    unsigned v = (i < BN) ? g_cnt[i] : 0u;
    sh[threadIdx.x] = v;
    __syncthreads();
    for (int o = 1; o < SCAN_B; o <<= 1) {
        unsigned t = (threadIdx.x >= o) ? sh[threadIdx.x - o] : 0u;
        __syncthreads();
        sh[threadIdx.x] += t;
        __syncthreads();
    }
    if (i < BN) g_off[i] = sh[threadIdx.x] - v;
    if (threadIdx.x == SCAN_B - 1) g_bsum[blockIdx.x] = sh[SCAN_B - 1];
}
__global__ void k_scanB() {
    __shared__ unsigned sh[SCAN_B];
    int i = threadIdx.x;
    unsigned v = (i < SCAN_NBLK) ? g_bsum[i] : 0u;
    sh[i] = v;
    __syncthreads();
    for (int o = 1; o < SCAN_B; o <<= 1) {
        unsigned t = (i >= o) ? sh[i - o] : 0u;
        __syncthreads();
        sh[i] += t;
        __syncthreads();
    }
    if (i < SCAN_NBLK) g_boff[i] = sh[i] - v;
}
__global__ void k_scanC() {
    int i = blockIdx.x * SCAN_B + threadIdx.x;
    if (i < BN) {
        unsigned o = g_off[i] + g_boff[blockIdx.x];
        g_off[i] = o;
        g_offcnt[i] = make_uint2(o, g_cnt[i]);
    }
}

// ---------------------------------------------------------------------------
// scatter edges into src-sorted buckets; one packed STG.128 per edge
// ---------------------------------------------------------------------------
__global__ __launch_bounds__(256) void k_scatter(const int* __restrict__ ei,
                                                 const int* __restrict__ bi) {
    int e = blockIdx.x * blockDim.x + threadIdx.x;
    if (e >= EE) return;
    int s = ei[e];
    int d = ei[EE + e];
    int b = bi[e];
    int gs = b * NN + s;
    int gd = b * NN + d;
    float a = g_attexp[e] / (g_attsum[gd] + 1e-9f);
    unsigned pos = g_off[gs] + atomicAdd(&g_cur[gs], 1u);
    g_meta[pos] = make_int4(gd, e, __float_as_int(a), 0);
}

// ---------------------------------------------------------------------------
// gather: one warp per src node. Batch-of-8 predicated edges (P(deg>8)=0.4%).
// ---------------------------------------------------------------------------
__global__ __launch_bounds__(256) void k_gather(const float* __restrict__ x,
                                                const float* __restrict__ e_emb) {
    int gs = (int)((blockIdx.x * blockDim.x + threadIdx.x) >> 5);
    int lane = threadIdx.x & 31;
    if (gs >= BN) return;
    uint2 oc = g_offcnt[gs];
    unsigned off = oc.x;
    unsigned end = off + oc.y;

    float4 ya = make_float4(0.f, 0.f, 0.f, 0.f);
    float4 ua = make_float4(0.f, 0.f, 0.f, 0.f);
    float asum = 0.f;
    const int4 mz = make_int4(0, 0, 0, 0);

    for (unsigned p = off; p < end; p += 8) {
        int4 m[8];
        m[0] = g_meta[p];
        #pragma unroll
        for (int q = 1; q < 8; q++)
            m[q] = (p + q < end) ? g_meta[p + q] : mz;

        float4 xr[8];
        #pragma unroll
        for (int q = 0; q < 8; q++)
            xr[q] = ((const float4*)x)[(size_t)m[q].x * 32 + lane];

        if (lane < 16) {
            #pragma unroll
            for (int q = 0; q < 8; q++) {
                float a = __int_as_float(m[q].z);
                float4 ev = ((const float4*)e_emb)[(size_t)m[q].y * 16 + lane];
                ua.x += a * ev.x; ua.y += a * ev.y;
                ua.z += a * ev.z; ua.w += a * ev.w;
            }
        }
        #pragma unroll
        for (int q = 0; q < 8; q++) {
            float a = __int_as_float(m[q].z);
            ya.x += a * xr[q].x; ya.y += a * xr[q].y;
            ya.z += a * xr[q].z; ya.w += a * xr[q].w;
            asum += a;
        }
    }
    g_y4[(size_t)gs * 32 + lane] = ya;
    if (lane < 16) g_u4[(size_t)gs * 16 + lane] = ua;
    if (lane == 0) g_asum[gs] = asum;
}

// ---------------------------------------------------------------------------
// epilogue — NPB=32 nodes / 256-thread block. Thread: col c = t&127,
// node-group g16 = t>>7 (nodes 16*g16 .. 16*g16+15). Halves W L2 traffic.
// ---------------------------------------------------------------------------
__global__ __launch_bounds__(256) void k_epi(const float* __restrict__ Wv,
                                             const float* __restrict__ bv,
                                             const float* __restrict__ Wev,
                                             const float* __restrict__ bev,
                                             float* __restrict__ out) {
    __shared__ __align__(16) float yq[(DD + DE) * NPB];   // [192][32], 24.6 KB
    __shared__ float as[NPB];
    int t = threadIdx.x;
    int n0 = blockIdx.x * NPB;

    // transpose-load: thread (i = t&31 node, g = t>>5 chunk 0..7)
    {
        int i = t & 31, g = t >> 5;
        const float4* yrow = g_y4 + (size_t)(n0 + i) * 32 + g * 4;
        #pragma unroll
        for (int q = 0; q < 4; q++) {
            float4 v = yrow[q];
            int j = g * 16 + q * 4;
            yq[(j + 0) * NPB + i] = v.x;
            yq[(j + 1) * NPB + i] = v.y;
            yq[(j + 2) * NPB + i] = v.z;
            yq[(j + 3) * NPB + i] = v.w;
        }
        const float4* urow = g_u4 + (size_t)(n0 + i) * 16 + g * 2;
        #pragma unroll
        for (int q = 0; q < 2; q++) {
            float4 v = urow[q];
            int j = DD + g * 8 + q * 4;
            yq[(j + 0) * NPB + i] = v.x;
            yq[(j + 1) * NPB + i] = v.y;
            yq[(j + 2) * NPB + i] = v.z;
            yq[(j + 3) * NPB + i] = v.w;
        }
        if (t < NPB) as[t] = g_asum[n0 + t];
    }
    __syncthreads();

    int c = t & 127;
    int g16 = t >> 7;                 // node sub-group 0 or 1
    int ibase = g16 * 16;             // element offset in yq row
    unsigned long long acc[8] = {0, 0, 0, 0, 0, 0, 0, 0};

    #pragma unroll 4
    for (int j = 0; j < DD; j++) {
        unsigned long long w2 = pk2(Wv[j * DD + c]);
        const ulonglong2* yr = (const ulonglong2*)(yq + j * NPB + ibase);
        ulonglong2 p0 = yr[0], p1 = yr[1], p2 = yr[2], p3 = yr[3];
        ffma2(acc[0], p0.x, w2); ffma2(acc[1], p0.y, w2);
        ffma2(acc[2], p1.x, w2); ffma2(acc[3], p1.y, w2);
        ffma2(acc[4], p2.x, w2); ffma2(acc[5], p2.y, w2);
        ffma2(acc[6], p3.x, w2); ffma2(acc[7], p3.y, w2);
    }
    #pragma unroll 4
    for (int j = 0; j < DE; j++) {
        unsigned long long w2 = pk2(Wev[j * DD + c]);
        const ulonglong2* yr = (const ulonglong2*)(yq + (DD + j) * NPB + ibase);
        ulonglong2 p0 = yr[0], p1 = yr[1], p2 = yr[2], p3 = yr[3];
        ffma2(acc[0], p0.x, w2); ffma2(acc[1], p0.y, w2);
        ffma2(acc[2], p1.x, w2); ffma2(acc[3], p1.y, w2);
        ffma2(acc[4], p2.x, w2); ffma2(acc[5], p2.y, w2);
        ffma2(acc[6], p3.x, w2); ffma2(acc[7], p3.y, w2);
    }

    float bb = bv[c] + bev[c];
    #pragma unroll
    for (int m = 0; m < 8; m++) {
        float lo, hi;
        asm("mov.b64 {%0, %1}, %2;" : "=f"(lo), "=f"(hi) : "l"(acc[m]));
        int n = n0 + ibase + 2 * m;
        out[(size_t)(n + 0) * DD + c] = lo + as[ibase + 2 * m + 0] * bb;
        out[(size_t)(n + 1) * DD + c] = hi + as[ibase + 2 * m + 1] * bb;
    }
}

// ---------------------------------------------------------------------------
extern "C" void kernel_launch(void* const* d_in, const int* in_sizes, int n_in,
                              void* d_out, int out_size) {
    const float* x     = (const float*)d_in[0];
    const int*   ei    = (const int*)d_in[1];
    const float* e_emb = (const float*)d_in[2];
    const int*   bi    = (const int*)d_in[3];

    int wb = 4;
    if (n_in >= 16 && in_sizes[4] <= 1) wb = 5;
    const float* Wq  = (const float*)d_in[wb + 0];
    const float* bq  = (const float*)d_in[wb + 1];
    const float* Wk  = (const float*)d_in[wb + 2];
    const float* bk  = (const float*)d_in[wb + 3];
    const float* Wv  = (const float*)d_in[wb + 4];
    const float* bv  = (const float*)d_in[wb + 5];
    const float* Wew = (const float*)d_in[wb + 6];
    const float* bew = (const float*)d_in[wb + 7];
    const float* Wev = (const float*)d_in[wb + 8];
    const float* bev = (const float*)d_in[wb + 9];
    const float* Wa  = (const float*)d_in[wb + 10];

    float* out = (float*)d_out;

    k_prep<<<1, 128>>>(Wq, Wk, Wew, bq, bk, bew, Wa);
    k_node<<<BN / 8, 256>>>(x);
    k_edge1<<<(EE * 4) / 128, 128>>>(ei, bi, e_emb);
    k_scanA<<<SCAN_NBLK, SCAN_B>>>();
    k_scanB<<<1, SCAN_B>>>();
    k_scanC<<<SCAN_NBLK, SCAN_B>>>();
    k_scatter<<<(EE + 255) / 256, 256>>>(ei, bi);
    k_gather<<<BN / 8, 256>>>(x, e_emb);
    k_epi<<<BN / NPB, 256>>>(Wv, bv, Wev, bev, out);
    (void)out_size;
}

// round 9
// speedup vs baseline: 1.1227x; 1.1227x over previous
#include <cuda_runtime.h>
#include <cuda_bf16.h>
#include <math.h>

#define BB 4
#define NN 50000
#define BN 200000          // BB*NN
#define EE 600000
#define DD 128
#define DE 64
#define NPB 32             // nodes per epilogue tile
#define EPI_TILES (BN / NPB)           // 6250
#define EPI_GRID 148
#define WS_F ((DD + DE) * DD)          // 24576 floats (Wv+Wev staged)
#define YQ_F ((DD + DE) * NPB)         // 6144 floats
#define EPI_SMEM ((WS_F + YQ_F + NPB) * 4)   // 123,008 B
#define SCAN_B 512
#define SCAN_NBLK ((BN + SCAN_B - 1) / SCAN_B)   // 391

// ---- scratch: static __device__ arrays only ----
__device__ float4 g_y4[(size_t)BN * 32];   // Σ alpha * x[dst]  per src (102.4 MB)
__device__ float4 g_u4[(size_t)BN * 16];   // Σ alpha * e_emb   per src (51.2 MB)
__device__ float  g_asum[BN];              // Σ alpha           per src
__device__ float  g_attsum[BN];            // Σ exp(logit)      per dst
__device__ float  g_attexp[EE];
__device__ float  g_qa[BN];
__device__ float  g_ka[BN];
__device__ float4 g_wqa4[32];
__device__ float4 g_wka4[32];
__device__ float4 g_wea4[16];
__device__ float  g_cb[1];
// CSR build
__device__ unsigned g_cnt[BN];
__device__ unsigned g_off[BN];
__device__ unsigned g_cur[BN];
__device__ unsigned g_bsum[SCAN_NBLK];
__device__ unsigned g_boff[SCAN_NBLK];
__device__ int4     g_meta[EE];            // sorted-by-src: {gd, eid, alpha_bits, 0}

__device__ __forceinline__ void redg(float* p, float v) {
    unsigned long long gp = (unsigned long long)__cvta_generic_to_global(p);
    asm volatile("red.global.add.f32 [%0], %1;" :: "l"(gp), "f"(v) : "memory");
}
__device__ __forceinline__ void redgu(unsigned* p, unsigned v) {
    unsigned long long gp = (unsigned long long)__cvta_generic_to_global(p);
    asm volatile("red.global.add.u32 [%0], %1;" :: "l"(gp), "r"(v) : "memory");
}
__device__ __forceinline__ unsigned long long pk2(float x) {
    unsigned long long r;
    asm("mov.b64 %0, {%1, %1};" : "=l"(r) : "f"(x));
    return r;
}
__device__ __forceinline__ void ffma2(unsigned long long& d, unsigned long long a,
                                      unsigned long long b) {
    asm("fma.rn.f32x2 %0, %1, %2, %0;" : "+l"(d) : "l"(a), "l"(b));
}

// ---------------------------------------------------------------------------
__global__ void k_prep(const float* __restrict__ Wq, const float* __restrict__ Wk,
                       const float* __restrict__ Wew,
                       const float* __restrict__ bq, const float* __restrict__ bk,
                       const float* __restrict__ bew, const float* __restrict__ Wa) {
    int j = threadIdx.x;
    float aq = 0.f, ak = 0.f;
    for (int k = 0; k < DD; k++) {
        float wa = Wa[k];
        aq += Wq[j * DD + k] * wa;
        ak += Wk[j * DD + k] * wa;
    }
    ((float*)g_wqa4)[j] = aq;
    ((float*)g_wka4)[j] = ak;
    if (j < DE) {
        float ae = 0.f;
        for (int k = 0; k < DD; k++) ae += Wew[j * DD + k] * Wa[k];
        ((float*)g_wea4)[j] = ae;
    }
    if (j == 0) {
        float c = 0.f;
        for (int k = 0; k < DD; k++) c += (bq[k] + bk[k] + bew[k]) * Wa[k];
        g_cb[0] = c;
    }
}

__global__ void k_zero_small() {
    int i = blockIdx.x * blockDim.x + threadIdx.x;
    if (i < BN) { g_attsum[i] = 0.f; g_cnt[i] = 0u; g_cur[i] = 0u; }
}

// ---------------------------------------------------------------------------
__global__ __launch_bounds__(256) void k_node(const float* __restrict__ x) {
    int w = (int)((blockIdx.x * blockDim.x + threadIdx.x) >> 5);
    int lane = threadIdx.x & 31;
    if (w >= BN) return;
    float4 xv = ((const float4*)x)[(size_t)w * 32 + lane];
    float4 wq = g_wqa4[lane];
    float4 wk = g_wka4[lane];
    float pq = xv.x * wq.x + xv.y * wq.y + xv.z * wq.z + xv.w * wq.w;
    float pk = xv.x * wk.x + xv.y * wk.y + xv.z * wk.z + xv.w * wk.w;
    #pragma unroll
    for (int o = 16; o > 0; o >>= 1) {
        pq += __shfl_xor_sync(0xffffffffu, pq, o);
        pk += __shfl_xor_sync(0xffffffffu, pk, o);
    }
    if (lane == 0) { g_qa[w] = pq; g_ka[w] = pk; }
}

// ---------------------------------------------------------------------------
__global__ __launch_bounds__(128) void k_edge1(const int* __restrict__ ei,
                                               const int* __restrict__ bi,
                                               const float* __restrict__ e_emb) {
    int t = blockIdx.x * blockDim.x + threadIdx.x;
    int e = t >> 2;
    int sub = t & 3;
    if (e >= EE) return;
    const float4* er = (const float4*)(e_emb + (size_t)e * DE);
    float p = 0.f;
    #pragma unroll
    for (int i = 0; i < 4; i++) {
        float4 v  = er[sub * 4 + i];
        float4 wv = g_wea4[sub * 4 + i];
        p += v.x * wv.x + v.y * wv.y + v.z * wv.z + v.w * wv.w;
    }
    p += __shfl_xor_sync(0xffffffffu, p, 1);
    p += __shfl_xor_sync(0xffffffffu, p, 2);
    if (sub == 0) {
        int s = ei[e];
        int d = ei[EE + e];
        int b = bi[e];
        int gs = b * NN + s;
        int gd = b * NN + d;
        float logit = (g_qa[gs] + g_ka[gd] + p + g_cb[0]) * 0.25f;
        float ex = expf(logit);
        g_attexp[e] = ex;
        redg(&g_attsum[gd], ex);
        redgu(&g_cnt[gs], 1u);
    }
}

// ---------------------------------------------------------------------------
__global__ void k_scanA() {
    __shared__ unsigned sh[SCAN_B];
    int i = blockIdx.x * SCAN_B + threadIdx.x;
    unsigned v = (i < BN) ? g_cnt[i] : 0u;
    sh[threadIdx.x] = v;
    __syncthreads();
    for (int o = 1; o < SCAN_B; o <<= 1) {
        unsigned t = (threadIdx.x >= o) ? sh[threadIdx.x - o] : 0u;
        __syncthreads();
        sh[threadIdx.x] += t;
        __syncthreads();
    }
    if (i < BN) g_off[i] = sh[threadIdx.x] - v;
    if (threadIdx.x == SCAN_B - 1) g_bsum[blockIdx.x] = sh[SCAN_B - 1];
}
__global__ void k_scanB() {
    __shared__ unsigned sh[SCAN_B];
    int i = threadIdx.x;
    unsigned v = (i < SCAN_NBLK) ? g_bsum[i] : 0u;
    sh[i] = v;
    __syncthreads();
    for (int o = 1; o < SCAN_B; o <<= 1) {
        unsigned t = (i >= o) ? sh[i - o] : 0u;
        __syncthreads();
        sh[i] += t;
        __syncthreads();
    }
    if (i < SCAN_NBLK) g_boff[i] = sh[i] - v;
}
__global__ void k_scanC() {
    int i = blockIdx.x * SCAN_B + threadIdx.x;
    if (i < BN) g_off[i] += g_boff[blockIdx.x];
}

// ---------------------------------------------------------------------------
__global__ __launch_bounds__(256) void k_scatter(const int* __restrict__ ei,
                                                 const int* __restrict__ bi) {
    int e = blockIdx.x * blockDim.x + threadIdx.x;
    if (e >= EE) return;
    int s = ei[e];
    int d = ei[EE + e];
    int b = bi[e];
    int gs = b * NN + s;
    int gd = b * NN + d;
    float a = g_attexp[e] / (g_attsum[gd] + 1e-9f);
    unsigned pos = g_off[gs] + atomicAdd(&g_cur[gs], 1u);
    g_meta[pos] = make_int4(gd, e, __float_as_int(a), 0);
}

// ---------------------------------------------------------------------------
// gather: one warp per src node. Batch-of-4 predicated edges (R7 version).
// ---------------------------------------------------------------------------
__global__ __launch_bounds__(256) void k_gather(const float* __restrict__ x,
                                                const float* __restrict__ e_emb) {
    int gs = (int)((blockIdx.x * blockDim.x + threadIdx.x) >> 5);
    int lane = threadIdx.x & 31;
    if (gs >= BN) return;
    unsigned off = g_off[gs];
    unsigned end = off + g_cnt[gs];

    float4 ya = make_float4(0.f, 0.f, 0.f, 0.f);
    float4 ua = make_float4(0.f, 0.f, 0.f, 0.f);
    float asum = 0.f;
    const int4 mz = make_int4(0, 0, 0, 0);

    for (unsigned p = off; p < end; p += 4) {
        int4 m0 = g_meta[p];
        int4 m1 = (p + 1 < end) ? g_meta[p + 1] : mz;
        int4 m2 = (p + 2 < end) ? g_meta[p + 2] : mz;
        int4 m3 = (p + 3 < end) ? g_meta[p + 3] : mz;
        float a0 = __int_as_float(m0.z);
        float a1 = __int_as_float(m1.z);
        float a2 = __int_as_float(m2.z);
        float a3 = __int_as_float(m3.z);

        float4 x0 = ((const float4*)x)[(size_t)m0.x * 32 + lane];
        float4 x1 = ((const float4*)x)[(size_t)m1.x * 32 + lane];
        float4 x2 = ((const float4*)x)[(size_t)m2.x * 32 + lane];
        float4 x3 = ((const float4*)x)[(size_t)m3.x * 32 + lane];

        if (lane < 16) {
            float4 e0 = ((const float4*)e_emb)[(size_t)m0.y * 16 + lane];
            float4 e1 = ((const float4*)e_emb)[(size_t)m1.y * 16 + lane];
            float4 e2 = ((const float4*)e_emb)[(size_t)m2.y * 16 + lane];
            float4 e3 = ((const float4*)e_emb)[(size_t)m3.y * 16 + lane];
            ua.x += a0 * e0.x + a1 * e1.x + a2 * e2.x + a3 * e3.x;
            ua.y += a0 * e0.y + a1 * e1.y + a2 * e2.y + a3 * e3.y;
            ua.z += a0 * e0.z + a1 * e1.z + a2 * e2.z + a3 * e3.z;
            ua.w += a0 * e0.w + a1 * e1.w + a2 * e2.w + a3 * e3.w;
        }

        ya.x += a0 * x0.x + a1 * x1.x + a2 * x2.x + a3 * x3.x;
        ya.y += a0 * x0.y + a1 * x1.y + a2 * x2.y + a3 * x3.y;
        ya.z += a0 * x0.z + a1 * x1.z + a2 * x2.z + a3 * x3.z;
        ya.w += a0 * x0.w + a1 * x1.w + a2 * x2.w + a3 * x3.w;
        asum += a0 + a1 + a2 + a3;
    }
    g_y4[(size_t)gs * 32 + lane] = ya;
    if (lane < 16) g_u4[(size_t)gs * 16 + lane] = ua;
    if (lane == 0) g_asum[gs] = asum;
}

// ---------------------------------------------------------------------------
// epilogue — PERSISTENT: 148 blocks, W staged once in smem, block-strided
// 32-node tiles, register-prefetch double buffering of y/u.
// ---------------------------------------------------------------------------
__global__ __launch_bounds__(256) void k_epi(const float* __restrict__ Wv,
                                             const float* __restrict__ bv,
                                             const float* __restrict__ Wev,
                                             const float* __restrict__ bev,
                                             float* __restrict__ out) {
    extern __shared__ __align__(16) float sm[];
    float* ws = sm;                    // [192][128] staged Wv;Wev
    float* yq = sm + WS_F;             // [192][NPB] transposed tile
    float* as = sm + WS_F + YQ_F;      // [NPB]
    int t = threadIdx.x;

    // ---- stage weights once ----
    {
        float4* ws4 = (float4*)ws;
        const float4* wv4 = (const float4*)Wv;
        #pragma unroll
        for (int k = 0; k < 16; k++) ws4[t + k * 256] = wv4[t + k * 256];
        float4* we4 = (float4*)(ws + DD * DD);
        const float4* wev4 = (const float4*)Wev;
        #pragma unroll
        for (int k = 0; k < 8; k++) we4[t + k * 256] = wev4[t + k * 256];
    }
    int c = t & 127, g16 = t >> 7, ibase = g16 * 16;
    float bb = bv[c] + bev[c];
    int i = t & 31, g = t >> 5;

    // ---- prefetch first tile into registers ----
    int tile = blockIdx.x;
    float4 py[4], pu[2];
    float pa = 0.f;
    {
        int n0 = tile * NPB;
        const float4* yrow = g_y4 + (size_t)(n0 + i) * 32 + g * 4;
        #pragma unroll
        for (int q = 0; q < 4; q++) py[q] = yrow[q];
        const float4* urow = g_u4 + (size_t)(n0 + i) * 16 + g * 2;
        #pragma unroll
        for (int q = 0; q < 2; q++) pu[q] = urow[q];
        if (t < NPB) pa = g_asum[tile * NPB + t];
    }

    for (; tile < EPI_TILES; tile += EPI_GRID) {
        __syncthreads();                       // prior compute done reading yq/as
        // commit prefetched tile (transposed)
        #pragma unroll
        for (int q = 0; q < 4; q++) {
            float4 v = py[q];
            int j = g * 16 + q * 4;
            yq[(j + 0) * NPB + i] = v.x;
            yq[(j + 1) * NPB + i] = v.y;
            yq[(j + 2) * NPB + i] = v.z;
            yq[(j + 3) * NPB + i] = v.w;
        }
        #pragma unroll
        for (int q = 0; q < 2; q++) {
            float4 v = pu[q];
            int j = DD + g * 8 + q * 4;
            yq[(j + 0) * NPB + i] = v.x;
            yq[(j + 1) * NPB + i] = v.y;
            yq[(j + 2) * NPB + i] = v.z;
            yq[(j + 3) * NPB + i] = v.w;
        }
        if (t < NPB) as[t] = pa;
        __syncthreads();

        // prefetch NEXT tile (overlaps with compute below)
        {
            int nt = tile + EPI_GRID;
            int pf = (nt < EPI_TILES) ? nt : tile;   // keep addresses valid
            int n0 = pf * NPB;
            const float4* yrow = g_y4 + (size_t)(n0 + i) * 32 + g * 4;
            #pragma unroll
            for (int q = 0; q < 4; q++) py[q] = yrow[q];
            const float4* urow = g_u4 + (size_t)(n0 + i) * 16 + g * 2;
            #pragma unroll
            for (int q = 0; q < 2; q++) pu[q] = urow[q];
            if (t < NPB) pa = g_asum[n0 + t];
        }

        // compute: 192-dim contraction, weights from smem, f32x2 FMA
        unsigned long long acc[8] = {0, 0, 0, 0, 0, 0, 0, 0};
        #pragma unroll 4
        for (int j = 0; j < DD + DE; j++) {
            unsigned long long w2 = pk2(ws[j * DD + c]);
            const ulonglong2* yr = (const ulonglong2*)(yq + j * NPB + ibase);
            ulonglong2 p0 = yr[0], p1 = yr[1], p2 = yr[2], p3 = yr[3];
            ffma2(acc[0], p0.x, w2); ffma2(acc[1], p0.y, w2);
            ffma2(acc[2], p1.x, w2); ffma2(acc[3], p1.y, w2);
            ffma2(acc[4], p2.x, w2); ffma2(acc[5], p2.y, w2);
            ffma2(acc[6], p3.x, w2); ffma2(acc[7], p3.y, w2);
        }

        int n0 = tile * NPB;
        #pragma unroll
        for (int m = 0; m < 8; m++) {
            float lo, hi;
            asm("mov.b64 {%0, %1}, %2;" : "=f"(lo), "=f"(hi) : "l"(acc[m]));
            int n = n0 + ibase + 2 * m;
            out[(size_t)(n + 0) * DD + c] = lo + as[ibase + 2 * m + 0] * bb;
            out[(size_t)(n + 1) * DD + c] = hi + as[ibase + 2 * m + 1] * bb;
        }
    }
}

// ---------------------------------------------------------------------------
extern "C" void kernel_launch(void* const* d_in, const int* in_sizes, int n_in,
                              void* d_out, int out_size) {
    const float* x     = (const float*)d_in[0];
    const int*   ei    = (const int*)d_in[1];
    const float* e_emb = (const float*)d_in[2];
    const int*   bi    = (const int*)d_in[3];

    int wb = 4;
    if (n_in >= 16 && in_sizes[4] <= 1) wb = 5;
    const float* Wq  = (const float*)d_in[wb + 0];
    const float* bq  = (const float*)d_in[wb + 1];
    const float* Wk  = (const float*)d_in[wb + 2];
    const float* bk  = (const float*)d_in[wb + 3];
    const float* Wv  = (const float*)d_in[wb + 4];
    const float* bv  = (const float*)d_in[wb + 5];
    const float* Wew = (const float*)d_in[wb + 6];
    const float* bew = (const float*)d_in[wb + 7];
    const float* Wev = (const float*)d_in[wb + 8];
    const float* bev = (const float*)d_in[wb + 9];
    const float* Wa  = (const float*)d_in[wb + 10];

    float* out = (float*)d_out;

    static int smem_set = 0;
    if (!smem_set) {
        cudaFuncSetAttribute(k_epi, cudaFuncAttributeMaxDynamicSharedMemorySize,
                             EPI_SMEM);
        smem_set = 1;
    }

    k_prep<<<1, 128>>>(Wq, Wk, Wew, bq, bk, bew, Wa);
    k_zero_small<<<(BN + 255) / 256, 256>>>();
    k_node<<<BN / 8, 256>>>(x);
    k_edge1<<<(EE * 4) / 128, 128>>>(ei, bi, e_emb);
    k_scanA<<<SCAN_NBLK, SCAN_B>>>();
    k_scanB<<<1, SCAN_B>>>();
    k_scanC<<<SCAN_NBLK, SCAN_B>>>();
    k_scatter<<<(EE + 255) / 256, 256>>>(ei, bi);
    k_gather<<<BN / 8, 256>>>(x, e_emb);
    k_epi<<<EPI_GRID, 256, EPI_SMEM>>>(Wv, bv, Wev, bev, out);
    (void)out_size;
}

// round 10
// speedup vs baseline: 1.2393x; 1.1038x over previous
#include <cuda_runtime.h>
#include <cuda_bf16.h>
#include <math.h>

#define BB 4
#define NN 50000
#define BN 200000          // BB*NN
#define EE 600000
#define DD 128
#define DE 64
#define NPB 16             // nodes per epilogue block (R7 config)
#define SCAN_B 512
#define SCAN_NBLK ((BN + SCAN_B - 1) / SCAN_B)   // 391

// ---- scratch: static __device__ arrays only ----
__device__ float4 g_y4[(size_t)BN * 32];   // Σ alpha * x[dst]  per src (102.4 MB)
__device__ float4 g_u4[(size_t)BN * 16];   // Σ alpha * e_emb   per src (51.2 MB)
__device__ float  g_asum[BN];              // Σ alpha           per src
__device__ float  g_attsum[BN];            // Σ exp(logit)      per dst
__device__ float  g_attexp[EE];
__device__ float  g_qa[BN];
__device__ float  g_ka[BN];
__device__ float4 g_wqa4[32];
__device__ float4 g_wka4[32];
__device__ float4 g_wea4[16];
__device__ float  g_cb[1];
// CSR build
__device__ unsigned g_cnt[BN];
__device__ unsigned g_off[BN];
__device__ unsigned g_cur[BN];
__device__ uint2    g_offcnt[BN];          // packed {off, cnt} for gather
__device__ unsigned g_bsum[SCAN_NBLK];
__device__ unsigned g_boff[SCAN_NBLK];
__device__ int4     g_meta[EE];            // sorted-by-src: {gd, eid, alpha_bits, 0}

__device__ __forceinline__ void redg(float* p, float v) {
    unsigned long long gp = (unsigned long long)__cvta_generic_to_global(p);
    asm volatile("red.global.add.f32 [%0], %1;" :: "l"(gp), "f"(v) : "memory");
}
__device__ __forceinline__ void redgu(unsigned* p, unsigned v) {
    unsigned long long gp = (unsigned long long)__cvta_generic_to_global(p);
    asm volatile("red.global.add.u32 [%0], %1;" :: "l"(gp), "r"(v) : "memory");
}
__device__ __forceinline__ unsigned long long pk2(float x) {
    unsigned long long r;
    asm("mov.b64 %0, {%1, %1};" : "=l"(r) : "f"(x));
    return r;
}
__device__ __forceinline__ void ffma2(unsigned long long& d, unsigned long long a,
                                      unsigned long long b) {
    asm("fma.rn.f32x2 %0, %1, %2, %0;" : "+l"(d) : "l"(a), "l"(b));
}

// ---------------------------------------------------------------------------
// K0: fold Wa. Thread-per-output, contiguous float4 row reads, 2x256 threads.
//   task id j: [0,128) wqa | [128,256) wka | [256,320) wea | 320 cb
// ---------------------------------------------------------------------------
__global__ __launch_bounds__(256) void k_prep(const float* __restrict__ Wq,
                                              const float* __restrict__ Wk,
                                              const float* __restrict__ Wew,
                                              const float* __restrict__ bq,
                                              const float* __restrict__ bk,
                                              const float* __restrict__ bew,
                                              const float* __restrict__ Wa) {
    int j = blockIdx.x * blockDim.x + threadIdx.x;
    const float4* wa4 = (const float4*)Wa;
    if (j < 128) {
        const float4* row = (const float4*)(Wq + (size_t)j * DD);
        float s = 0.f;
        #pragma unroll
        for (int k = 0; k < 32; k++) {
            float4 r = row[k], w = wa4[k];
            s += r.x * w.x + r.y * w.y + r.z * w.z + r.w * w.w;
        }
        ((float*)g_wqa4)[j] = s;
    } else if (j < 256) {
        const float4* row = (const float4*)(Wk + (size_t)(j - 128) * DD);
        float s = 0.f;
        #pragma unroll
        for (int k = 0; k < 32; k++) {
            float4 r = row[k], w = wa4[k];
            s += r.x * w.x + r.y * w.y + r.z * w.z + r.w * w.w;
        }
        ((float*)g_wka4)[j - 128] = s;
    } else if (j < 320) {
        const float4* row = (const float4*)(Wew + (size_t)(j - 256) * DD);
        float s = 0.f;
        #pragma unroll
        for (int k = 0; k < 32; k++) {
            float4 r = row[k], w = wa4[k];
            s += r.x * w.x + r.y * w.y + r.z * w.z + r.w * w.w;
        }
        ((float*)g_wea4)[j - 256] = s;
    } else if (j == 320) {
        float c = 0.f;
        for (int k = 0; k < DD; k++) c += (bq[k] + bk[k] + bew[k]) * Wa[k];
        g_cb[0] = c;
    }
}

// ---------------------------------------------------------------------------
// K1: per-node scalars + fused zeroing (attsum/cnt/cur)
// ---------------------------------------------------------------------------
__global__ __launch_bounds__(256) void k_node(const float* __restrict__ x) {
    int lin = blockIdx.x * blockDim.x + threadIdx.x;
    if (lin < BN) { g_attsum[lin] = 0.f; g_cnt[lin] = 0u; g_cur[lin] = 0u; }
    int w = lin >> 5;
    int lane = threadIdx.x & 31;
    if (w >= BN) return;
    float4 xv = ((const float4*)x)[(size_t)w * 32 + lane];
    float4 wq = g_wqa4[lane];
    float4 wk = g_wka4[lane];
    float pq = xv.x * wq.x + xv.y * wq.y + xv.z * wq.z + xv.w * wq.w;
    float pk = xv.x * wk.x + xv.y * wk.y + xv.z * wk.z + xv.w * wk.w;
    #pragma unroll
    for (int o = 16; o > 0; o >>= 1) {
        pq += __shfl_xor_sync(0xffffffffu, pq, o);
        pk += __shfl_xor_sync(0xffffffffu, pk, o);
    }
    if (lane == 0) { g_qa[w] = pq; g_ka[w] = pk; }
}

// ---------------------------------------------------------------------------
// edge pass 1: logit/exp + attsum red + src-degree histogram
// ---------------------------------------------------------------------------
__global__ __launch_bounds__(128) void k_edge1(const int* __restrict__ ei,
                                               const int* __restrict__ bi,
                                               const float* __restrict__ e_emb) {
    int t = blockIdx.x * blockDim.x + threadIdx.x;
    int e = t >> 2;
    int sub = t & 3;
    if (e >= EE) return;
    const float4* er = (const float4*)(e_emb + (size_t)e * DE);
    float p = 0.f;
    #pragma unroll
    for (int i = 0; i < 4; i++) {
        float4 v  = er[sub * 4 + i];
        float4 wv = g_wea4[sub * 4 + i];
        p += v.x * wv.x + v.y * wv.y + v.z * wv.z + v.w * wv.w;
    }
    p += __shfl_xor_sync(0xffffffffu, p, 1);
    p += __shfl_xor_sync(0xffffffffu, p, 2);
    if (sub == 0) {
        int s = ei[e];
        int d = ei[EE + e];
        int b = bi[e];
        int gs = b * NN + s;
        int gd = b * NN + d;
        float logit = (g_qa[gs] + g_ka[gd] + p + g_cb[0]) * 0.25f;
        float ex = expf(logit);
        g_attexp[e] = ex;
        redg(&g_attsum[gd], ex);
        redgu(&g_cnt[gs], 1u);
    }
}

// ---------------------------------------------------------------------------
// 3-kernel exclusive scan of g_cnt -> g_off (+ packed offcnt)
// ---------------------------------------------------------------------------
__global__ void k_scanA() {
    __shared__ unsigned sh[SCAN_B];
    int i = blockIdx.x * SCAN_B + threadIdx.x;
    unsigned v = (i < BN) ? g_cnt[i] : 0u;
    sh[threadIdx.x] = v;
    __syncthreads();
    for (int o = 1; o < SCAN_B; o <<= 1) {
        unsigned t = (threadIdx.x >= o) ? sh[threadIdx.x - o] : 0u;
        __syncthreads();
        sh[threadIdx.x] += t;
        __syncthreads();
    }
    if (i < BN) g_off[i] = sh[threadIdx.x] - v;
    if (threadIdx.x == SCAN_B - 1) g_bsum[blockIdx.x] = sh[SCAN_B - 1];
}
__global__ void k_scanB() {
    __shared__ unsigned sh[SCAN_B];
    int i = threadIdx.x;
    unsigned v = (i < SCAN_NBLK) ? g_bsum[i] : 0u;
    sh[i] = v;
    __syncthreads();
    for (int o = 1; o < SCAN_B; o <<= 1) {
        unsigned t = (i >= o) ? sh[i - o] : 0u;
        __syncthreads();
        sh[i] += t;
        __syncthreads();
    }
    if (i < SCAN_NBLK) g_boff[i] = sh[i] - v;
}
__global__ void k_scanC() {
    int i = blockIdx.x * SCAN_B + threadIdx.x;
    if (i < BN) {
        unsigned o = g_off[i] + g_boff[blockIdx.x];
        g_off[i] = o;
        g_offcnt[i] = make_uint2(o, g_cnt[i]);
    }
}

// ---------------------------------------------------------------------------
// scatter edges into src-sorted buckets; one packed STG.128 per edge
// ---------------------------------------------------------------------------
__global__ __launch_bounds__(256) void k_scatter(const int* __restrict__ ei,
                                                 const int* __restrict__ bi) {
    int e = blockIdx.x * blockDim.x + threadIdx.x;
    if (e >= EE) return;
    int s = ei[e];
    int d = ei[EE + e];
    int b = bi[e];
    int gs = b * NN + s;
    int gd = b * NN + d;
    float a = g_attexp[e] / (g_attsum[gd] + 1e-9f);
    unsigned pos = g_off[gs] + atomicAdd(&g_cur[gs], 1u);
    g_meta[pos] = make_int4(gd, e, __float_as_int(a), 0);
}

// ---------------------------------------------------------------------------
// gather: one warp per src node. Batch-of-4 predicated edges (R7-proven).
// e_emb loads use streaming hint (read-once data).
// ---------------------------------------------------------------------------
__global__ __launch_bounds__(256) void k_gather(const float* __restrict__ x,
                                                const float* __restrict__ e_emb) {
    int gs = (int)((blockIdx.x * blockDim.x + threadIdx.x) >> 5);
    int lane = threadIdx.x & 31;
    if (gs >= BN) return;
    uint2 oc = g_offcnt[gs];
    unsigned off = oc.x;
    unsigned end = off + oc.y;

    float4 ya = make_float4(0.f, 0.f, 0.f, 0.f);
    float4 ua = make_float4(0.f, 0.f, 0.f, 0.f);
    float asum = 0.f;
    const int4 mz = make_int4(0, 0, 0, 0);

    for (unsigned p = off; p < end; p += 4) {
        int4 m0 = g_meta[p];
        int4 m1 = (p + 1 < end) ? g_meta[p + 1] : mz;
        int4 m2 = (p + 2 < end) ? g_meta[p + 2] : mz;
        int4 m3 = (p + 3 < end) ? g_meta[p + 3] : mz;
        float a0 = __int_as_float(m0.z);
        float a1 = __int_as_float(m1.z);
        float a2 = __int_as_float(m2.z);
        float a3 = __int_as_float(m3.z);

        float4 x0 = ((const float4*)x)[(size_t)m0.x * 32 + lane];
        float4 x1 = ((const float4*)x)[(size_t)m1.x * 32 + lane];
        float4 x2 = ((const float4*)x)[(size_t)m2.x * 32 + lane];
        float4 x3 = ((const float4*)x)[(size_t)m3.x * 32 + lane];

        if (lane < 16) {
            float4 e0 = __ldcs((const float4*)e_emb + (size_t)m0.y * 16 + lane);
            float4 e1 = __ldcs((const float4*)e_emb + (size_t)m1.y * 16 + lane);
            float4 e2 = __ldcs((const float4*)e_emb + (size_t)m2.y * 16 + lane);
            float4 e3 = __ldcs((const float4*)e_emb + (size_t)m3.y * 16 + lane);
            ua.x += a0 * e0.x + a1 * e1.x + a2 * e2.x + a3 * e3.x;
            ua.y += a0 * e0.y + a1 * e1.y + a2 * e2.y + a3 * e3.y;
            ua.z += a0 * e0.z + a1 * e1.z + a2 * e2.z + a3 * e3.z;
            ua.w += a0 * e0.w + a1 * e1.w + a2 * e2.w + a3 * e3.w;
        }

        ya.x += a0 * x0.x + a1 * x1.x + a2 * x2.x + a3 * x3.x;
        ya.y += a0 * x0.y + a1 * x1.y + a2 * x2.y + a3 * x3.y;
        ya.z += a0 * x0.z + a1 * x1.z + a2 * x2.z + a3 * x3.z;
        ya.w += a0 * x0.w + a1 * x1.w + a2 * x2.w + a3 * x3.w;
        asum += a0 + a1 + a2 + a3;
    }
    g_y4[(size_t)gs * 32 + lane] = ya;
    if (lane < 16) g_u4[(size_t)gs * 16 + lane] = ua;
    if (lane == 0) g_asum[gs] = asum;
}

// ---------------------------------------------------------------------------
// epilogue — R7-proven: NPB=16 nodes / 128-thread block, transposed smem,
// f32x2 FMA, weights from global (L1-resident across CTAs).
// ---------------------------------------------------------------------------
__global__ __launch_bounds__(128) void k_epi(const float* __restrict__ Wv,
                                             const float* __restrict__ bv,
                                             const float* __restrict__ Wev,
                                             const float* __restrict__ bev,
                                             float* __restrict__ out) {
    __shared__ __align__(16) float yq[(DD + DE) * NPB];
    __shared__ float as[NPB];
    int t = threadIdx.x;
    int n0 = blockIdx.x * NPB;

    {
        int i = t & 15, g = t >> 4;
        const float4* yrow = g_y4 + (size_t)(n0 + i) * 32 + g * 4;
        #pragma unroll
        for (int q = 0; q < 4; q++) {
            float4 v = yrow[q];
            int j = g * 16 + q * 4;
            yq[(j + 0) * NPB + i] = v.x;
            yq[(j + 1) * NPB + i] = v.y;
            yq[(j + 2) * NPB + i] = v.z;
            yq[(j + 3) * NPB + i] = v.w;
        }
        const float4* urow = g_u4 + (size_t)(n0 + i) * 16 + g * 2;
        #pragma unroll
        for (int q = 0; q < 2; q++) {
            float4 v = urow[q];
            int j = DD + g * 8 + q * 4;
            yq[(j + 0) * NPB + i] = v.x;
            yq[(j + 1) * NPB + i] = v.y;
            yq[(j + 2) * NPB + i] = v.z;
            yq[(j + 3) * NPB + i] = v.w;
        }
        if (t < NPB) as[t] = g_asum[n0 + t];
    }
    __syncthreads();

    int c = t;
    unsigned long long acc[8] = {0, 0, 0, 0, 0, 0, 0, 0};

    #pragma unroll 4
    for (int j = 0; j < DD; j++) {
        unsigned long long w2 = pk2(Wv[j * DD + c]);
        const ulonglong2* yr = (const ulonglong2*)(yq + j * NPB);
        ulonglong2 p0 = yr[0], p1 = yr[1], p2 = yr[2], p3 = yr[3];
        ffma2(acc[0], p0.x, w2); ffma2(acc[1], p0.y, w2);
        ffma2(acc[2], p1.x, w2); ffma2(acc[3], p1.y, w2);
        ffma2(acc[4], p2.x, w2); ffma2(acc[5], p2.y, w2);
        ffma2(acc[6], p3.x, w2); ffma2(acc[7], p3.y, w2);
    }
    #pragma unroll 4
    for (int j = 0; j < DE; j++) {
        unsigned long long w2 = pk2(Wev[j * DD + c]);
        const ulonglong2* yr = (const ulonglong2*)(yq + (DD + j) * NPB);
        ulonglong2 p0 = yr[0], p1 = yr[1], p2 = yr[2], p3 = yr[3];
        ffma2(acc[0], p0.x, w2); ffma2(acc[1], p0.y, w2);
        ffma2(acc[2], p1.x, w2); ffma2(acc[3], p1.y, w2);
        ffma2(acc[4], p2.x, w2); ffma2(acc[5], p2.y, w2);
        ffma2(acc[6], p3.x, w2); ffma2(acc[7], p3.y, w2);
    }

    float bb = bv[c] + bev[c];
    #pragma unroll
    for (int m = 0; m < 8; m++) {
        float lo, hi;
        asm("mov.b64 {%0, %1}, %2;" : "=f"(lo), "=f"(hi) : "l"(acc[m]));
        out[(size_t)(n0 + 2 * m + 0) * DD + c] = lo + as[2 * m + 0] * bb;
        out[(size_t)(n0 + 2 * m + 1) * DD + c] = hi + as[2 * m + 1] * bb;
    }
}

// ---------------------------------------------------------------------------
extern "C" void kernel_launch(void* const* d_in, const int* in_sizes, int n_in,
                              void* d_out, int out_size) {
    const float* x     = (const float*)d_in[0];
    const int*   ei    = (const int*)d_in[1];
    const float* e_emb = (const float*)d_in[2];
    const int*   bi    = (const int*)d_in[3];

    int wb = 4;
    if (n_in >= 16 && in_sizes[4] <= 1) wb = 5;
    const float* Wq  = (const float*)d_in[wb + 0];
    const float* bq  = (const float*)d_in[wb + 1];
    const float* Wk  = (const float*)d_in[wb + 2];
    const float* bk  = (const float*)d_in[wb + 3];
    const float* Wv  = (const float*)d_in[wb + 4];
    const float* bv  = (const float*)d_in[wb + 5];
    const float* Wew = (const float*)d_in[wb + 6];
    const float* bew = (const float*)d_in[wb + 7];
    const float* Wev = (const float*)d_in[wb + 8];
    const float* bev = (const float*)d_in[wb + 9];
    const float* Wa  = (const float*)d_in[wb + 10];

    float* out = (float*)d_out;

    k_prep<<<2, 256>>>(Wq, Wk, Wew, bq, bk, bew, Wa);
    k_node<<<BN / 8, 256>>>(x);
    k_edge1<<<(EE * 4) / 128, 128>>>(ei, bi, e_emb);
    k_scanA<<<SCAN_NBLK, SCAN_B>>>();
    k_scanB<<<1, SCAN_B>>>();
    k_scanC<<<SCAN_NBLK, SCAN_B>>>();
    k_scatter<<<(EE + 255) / 256, 256>>>(ei, bi);
    k_gather<<<BN / 8, 256>>>(x, e_emb);
    k_epi<<<BN / NPB, 128>>>(Wv, bv, Wev, bev, out);
    (void)out_size;
}

// round 11
// speedup vs baseline: 1.2720x; 1.0264x over previous
#include <cuda_runtime.h>
#include <cuda_bf16.h>
#include <math.h>

#define BB 4
#define NN 50000
#define BN 200000          // BB*NN
#define EE 600000
#define DD 128
#define DE 64
#define NPB 16             // nodes per epilogue block (R7 config)
#define GNPB 32            // nodes per gather block
#define GCAP 384           // staged meta capacity (P(overflow) ~ e^-96)
#define SCAN_B 512
#define SCAN_NBLK ((BN + SCAN_B - 1) / SCAN_B)   // 391

// ---- scratch: static __device__ arrays only ----
__device__ float4 g_y4[(size_t)BN * 32];   // Σ alpha * x[dst]  per src (102.4 MB)
__device__ float4 g_u4[(size_t)BN * 16];   // Σ alpha * e_emb   per src (51.2 MB)
__device__ float  g_asum[BN];              // Σ alpha           per src
__device__ float  g_attsum[BN];            // Σ exp(logit)      per dst
__device__ float  g_attexp[EE];
__device__ float  g_qa[BN];
__device__ float  g_ka[BN];
__device__ float4 g_wqa4[32];
__device__ float4 g_wka4[32];
__device__ float4 g_wea4[16];
__device__ float  g_cb[1];
// CSR build
__device__ unsigned g_cnt[BN];
__device__ unsigned g_off[BN];
__device__ unsigned g_cur[BN];
__device__ uint2    g_offcnt[BN];          // packed {off, cnt} for gather
__device__ unsigned g_bsum[SCAN_NBLK];
__device__ unsigned g_boff[SCAN_NBLK];
__device__ int4     g_meta[EE];            // sorted-by-src: {gd, eid, alpha_bits, 0}

__device__ __forceinline__ void redg(float* p, float v) {
    unsigned long long gp = (unsigned long long)__cvta_generic_to_global(p);
    asm volatile("red.global.add.f32 [%0], %1;" :: "l"(gp), "f"(v) : "memory");
}
__device__ __forceinline__ void redgu(unsigned* p, unsigned v) {
    unsigned long long gp = (unsigned long long)__cvta_generic_to_global(p);
    asm volatile("red.global.add.u32 [%0], %1;" :: "l"(gp), "r"(v) : "memory");
}
__device__ __forceinline__ unsigned long long pk2(float x) {
    unsigned long long r;
    asm("mov.b64 %0, {%1, %1};" : "=l"(r) : "f"(x));
    return r;
}
__device__ __forceinline__ void ffma2(unsigned long long& d, unsigned long long a,
                                      unsigned long long b) {
    asm("fma.rn.f32x2 %0, %1, %2, %0;" : "+l"(d) : "l"(a), "l"(b));
}

// ---------------------------------------------------------------------------
// K0: fold Wa. Thread-per-output, contiguous float4 row reads, 2x256 threads.
// ---------------------------------------------------------------------------
__global__ __launch_bounds__(256) void k_prep(const float* __restrict__ Wq,
                                              const float* __restrict__ Wk,
                                              const float* __restrict__ Wew,
                                              const float* __restrict__ bq,
                                              const float* __restrict__ bk,
                                              const float* __restrict__ bew,
                                              const float* __restrict__ Wa) {
    int j = blockIdx.x * blockDim.x + threadIdx.x;
    const float4* wa4 = (const float4*)Wa;
    if (j < 128) {
        const float4* row = (const float4*)(Wq + (size_t)j * DD);
        float s = 0.f;
        #pragma unroll
        for (int k = 0; k < 32; k++) {
            float4 r = row[k], w = wa4[k];
            s += r.x * w.x + r.y * w.y + r.z * w.z + r.w * w.w;
        }
        ((float*)g_wqa4)[j] = s;
    } else if (j < 256) {
        const float4* row = (const float4*)(Wk + (size_t)(j - 128) * DD);
        float s = 0.f;
        #pragma unroll
        for (int k = 0; k < 32; k++) {
            float4 r = row[k], w = wa4[k];
            s += r.x * w.x + r.y * w.y + r.z * w.z + r.w * w.w;
        }
        ((float*)g_wka4)[j - 128] = s;
    } else if (j < 320) {
        const float4* row = (const float4*)(Wew + (size_t)(j - 256) * DD);
        float s = 0.f;
        #pragma unroll
        for (int k = 0; k < 32; k++) {
            float4 r = row[k], w = wa4[k];
            s += r.x * w.x + r.y * w.y + r.z * w.z + r.w * w.w;
        }
        ((float*)g_wea4)[j - 256] = s;
    } else if (j == 320) {
        float c = 0.f;
        for (int k = 0; k < DD; k++) c += (bq[k] + bk[k] + bew[k]) * Wa[k];
        g_cb[0] = c;
    }
}

// ---------------------------------------------------------------------------
// K1: per-node scalars + fused zeroing (attsum/cnt/cur)
// ---------------------------------------------------------------------------
__global__ __launch_bounds__(256) void k_node(const float* __restrict__ x) {
    int lin = blockIdx.x * blockDim.x + threadIdx.x;
    if (lin < BN) { g_attsum[lin] = 0.f; g_cnt[lin] = 0u; g_cur[lin] = 0u; }
    int w = lin >> 5;
    int lane = threadIdx.x & 31;
    if (w >= BN) return;
    float4 xv = ((const float4*)x)[(size_t)w * 32 + lane];
    float4 wq = g_wqa4[lane];
    float4 wk = g_wka4[lane];
    float pq = xv.x * wq.x + xv.y * wq.y + xv.z * wq.z + xv.w * wq.w;
    float pk = xv.x * wk.x + xv.y * wk.y + xv.z * wk.z + xv.w * wk.w;
    #pragma unroll
    for (int o = 16; o > 0; o >>= 1) {
        pq += __shfl_xor_sync(0xffffffffu, pq, o);
        pk += __shfl_xor_sync(0xffffffffu, pk, o);
    }
    if (lane == 0) { g_qa[w] = pq; g_ka[w] = pk; }
}

// ---------------------------------------------------------------------------
// edge pass 1: logit/exp + attsum red + src-degree histogram
// ---------------------------------------------------------------------------
__global__ __launch_bounds__(128) void k_edge1(const int* __restrict__ ei,
                                               const int* __restrict__ bi,
                                               const float* __restrict__ e_emb) {
    int t = blockIdx.x * blockDim.x + threadIdx.x;
    int e = t >> 2;
    int sub = t & 3;
    if (e >= EE) return;
    const float4* er = (const float4*)(e_emb + (size_t)e * DE);
    float p = 0.f;
    #pragma unroll
    for (int i = 0; i < 4; i++) {
        float4 v  = er[sub * 4 + i];
        float4 wv = g_wea4[sub * 4 + i];
        p += v.x * wv.x + v.y * wv.y + v.z * wv.z + v.w * wv.w;
    }
    p += __shfl_xor_sync(0xffffffffu, p, 1);
    p += __shfl_xor_sync(0xffffffffu, p, 2);
    if (sub == 0) {
        int s = ei[e];
        int d = ei[EE + e];
        int b = bi[e];
        int gs = b * NN + s;
        int gd = b * NN + d;
        float logit = (g_qa[gs] + g_ka[gd] + p + g_cb[0]) * 0.25f;
        float ex = expf(logit);
        g_attexp[e] = ex;
        redg(&g_attsum[gd], ex);
        redgu(&g_cnt[gs], 1u);
    }
}

// ---------------------------------------------------------------------------
// 3-kernel exclusive scan of g_cnt -> g_off (+ packed offcnt)
// ---------------------------------------------------------------------------
__global__ void k_scanA() {
    __shared__ unsigned sh[SCAN_B];
    int i = blockIdx.x * SCAN_B + threadIdx.x;
    unsigned v = (i < BN) ? g_cnt[i] : 0u;
    sh[threadIdx.x] = v;
    __syncthreads();
    for (int o = 1; o < SCAN_B; o <<= 1) {
        unsigned t = (threadIdx.x >= o) ? sh[threadIdx.x - o] : 0u;
        __syncthreads();
        sh[threadIdx.x] += t;
        __syncthreads();
    }
    if (i < BN) g_off[i] = sh[threadIdx.x] - v;
    if (threadIdx.x == SCAN_B - 1) g_bsum[blockIdx.x] = sh[SCAN_B - 1];
}
__global__ void k_scanB() {
    __shared__ unsigned sh[SCAN_B];
    int i = threadIdx.x;
    unsigned v = (i < SCAN_NBLK) ? g_bsum[i] : 0u;
    sh[i] = v;
    __syncthreads();
    for (int o = 1; o < SCAN_B; o <<= 1) {
        unsigned t = (i >= o) ? sh[i - o] : 0u;
        __syncthreads();
        sh[i] += t;
        __syncthreads();
    }
    if (i < SCAN_NBLK) g_boff[i] = sh[i] - v;
}
__global__ void k_scanC() {
    int i = blockIdx.x * SCAN_B + threadIdx.x;
    if (i < BN) {
        unsigned o = g_off[i] + g_boff[blockIdx.x];
        g_off[i] = o;
        g_offcnt[i] = make_uint2(o, g_cnt[i]);
    }
}

// ---------------------------------------------------------------------------
// scatter edges into src-sorted buckets; one packed STG.128 per edge
// ---------------------------------------------------------------------------
__global__ __launch_bounds__(256) void k_scatter(const int* __restrict__ ei,
                                                 const int* __restrict__ bi) {
    int e = blockIdx.x * blockDim.x + threadIdx.x;
    if (e >= EE) return;
    int s = ei[e];
    int d = ei[EE + e];
    int b = bi[e];
    int gs = b * NN + s;
    int gd = b * NN + d;
    float a = g_attexp[e] / (g_attsum[gd] + 1e-9f);
    unsigned pos = g_off[gs] + atomicAdd(&g_cur[gs], 1u);
    g_meta[pos] = make_int4(gd, e, __float_as_int(a), 0);
}

// ---------------------------------------------------------------------------
// gather v2: block-cooperative CSR staging. 256 threads / 32 contiguous
// nodes; offcnt + meta slab loaded coalesced into smem, then 8 warps x
// 4 nodes run the batch-4 gather with meta from smem (no global chain).
// ---------------------------------------------------------------------------
__global__ __launch_bounds__(256) void k_gather(const float* __restrict__ x,
                                                const float* __restrict__ e_emb) {
    __shared__ uint2 sc[GNPB];
    __shared__ __align__(16) int4 smeta[GCAP];
    int t = threadIdx.x;
    int gs0 = blockIdx.x * GNPB;

    if (t < GNPB) sc[t] = g_offcnt[gs0 + t];
    __syncthreads();
    unsigned base = sc[0].x;
    unsigned total = sc[GNPB - 1].x + sc[GNPB - 1].y - base;
    bool fit = (total <= (unsigned)GCAP);
    if (fit) {
        for (unsigned i = t; i < total; i += 256) smeta[i] = g_meta[base + i];
    }
    __syncthreads();

    int w = t >> 5, lane = t & 31;
    const int4 mz = make_int4(0, 0, 0, 0);

    #pragma unroll
    for (int nn = 0; nn < 4; nn++) {
        int li = w * 4 + nn;
        int gs = gs0 + li;
        unsigned off = sc[li].x;
        unsigned end = off + sc[li].y;

        float4 ya = make_float4(0.f, 0.f, 0.f, 0.f);
        float4 ua = make_float4(0.f, 0.f, 0.f, 0.f);
        float asum = 0.f;

        for (unsigned p = off; p < end; p += 4) {
            int4 m0, m1, m2, m3;
            if (fit) {
                unsigned q = p - base;
                m0 = smeta[q];
                m1 = (p + 1 < end) ? smeta[q + 1] : mz;
                m2 = (p + 2 < end) ? smeta[q + 2] : mz;
                m3 = (p + 3 < end) ? smeta[q + 3] : mz;
            } else {
                m0 = g_meta[p];
                m1 = (p + 1 < end) ? g_meta[p + 1] : mz;
                m2 = (p + 2 < end) ? g_meta[p + 2] : mz;
                m3 = (p + 3 < end) ? g_meta[p + 3] : mz;
            }
            float a0 = __int_as_float(m0.z);
            float a1 = __int_as_float(m1.z);
            float a2 = __int_as_float(m2.z);
            float a3 = __int_as_float(m3.z);

            float4 x0 = ((const float4*)x)[(size_t)m0.x * 32 + lane];
            float4 x1 = ((const float4*)x)[(size_t)m1.x * 32 + lane];
            float4 x2 = ((const float4*)x)[(size_t)m2.x * 32 + lane];
            float4 x3 = ((const float4*)x)[(size_t)m3.x * 32 + lane];

            if (lane < 16) {
                float4 e0 = __ldcs((const float4*)e_emb + (size_t)m0.y * 16 + lane);
                float4 e1 = __ldcs((const float4*)e_emb + (size_t)m1.y * 16 + lane);
                float4 e2 = __ldcs((const float4*)e_emb + (size_t)m2.y * 16 + lane);
                float4 e3 = __ldcs((const float4*)e_emb + (size_t)m3.y * 16 + lane);
                ua.x += a0 * e0.x + a1 * e1.x + a2 * e2.x + a3 * e3.x;
                ua.y += a0 * e0.y + a1 * e1.y + a2 * e2.y + a3 * e3.y;
                ua.z += a0 * e0.z + a1 * e1.z + a2 * e2.z + a3 * e3.z;
                ua.w += a0 * e0.w + a1 * e1.w + a2 * e2.w + a3 * e3.w;
            }

            ya.x += a0 * x0.x + a1 * x1.x + a2 * x2.x + a3 * x3.x;
            ya.y += a0 * x0.y + a1 * x1.y + a2 * x2.y + a3 * x3.y;
            ya.z += a0 * x0.z + a1 * x1.z + a2 * x2.z + a3 * x3.z;
            ya.w += a0 * x0.w + a1 * x1.w + a2 * x2.w + a3 * x3.w;
            asum += a0 + a1 + a2 + a3;
        }
        g_y4[(size_t)gs * 32 + lane] = ya;
        if (lane < 16) g_u4[(size_t)gs * 16 + lane] = ua;
        if (lane == 0) g_asum[gs] = asum;
    }
}

// ---------------------------------------------------------------------------
// epilogue — R7-proven: NPB=16 nodes / 128-thread block, transposed smem,
// f32x2 FMA, weights from global (L1-resident across CTAs).
// ---------------------------------------------------------------------------
__global__ __launch_bounds__(128) void k_epi(const float* __restrict__ Wv,
                                             const float* __restrict__ bv,
                                             const float* __restrict__ Wev,
                                             const float* __restrict__ bev,
                                             float* __restrict__ out) {
    __shared__ __align__(16) float yq[(DD + DE) * NPB];
    __shared__ float as[NPB];
    int t = threadIdx.x;
    int n0 = blockIdx.x * NPB;

    {
        int i = t & 15, g = t >> 4;
        const float4* yrow = g_y4 + (size_t)(n0 + i) * 32 + g * 4;
        #pragma unroll
        for (int q = 0; q < 4; q++) {
            float4 v = yrow[q];
            int j = g * 16 + q * 4;
            yq[(j + 0) * NPB + i] = v.x;
            yq[(j + 1) * NPB + i] = v.y;
            yq[(j + 2) * NPB + i] = v.z;
            yq[(j + 3) * NPB + i] = v.w;
        }
        const float4* urow = g_u4 + (size_t)(n0 + i) * 16 + g * 2;
        #pragma unroll
        for (int q = 0; q < 2; q++) {
            float4 v = urow[q];
            int j = DD + g * 8 + q * 4;
            yq[(j + 0) * NPB + i] = v.x;
            yq[(j + 1) * NPB + i] = v.y;
            yq[(j + 2) * NPB + i] = v.z;
            yq[(j + 3) * NPB + i] = v.w;
        }
        if (t < NPB) as[t] = g_asum[n0 + t];
    }
    __syncthreads();

    int c = t;
    unsigned long long acc[8] = {0, 0, 0, 0, 0, 0, 0, 0};

    #pragma unroll 4
    for (int j = 0; j < DD; j++) {
        unsigned long long w2 = pk2(Wv[j * DD + c]);
        const ulonglong2* yr = (const ulonglong2*)(yq + j * NPB);
        ulonglong2 p0 = yr[0], p1 = yr[1], p2 = yr[2], p3 = yr[3];
        ffma2(acc[0], p0.x, w2); ffma2(acc[1], p0.y, w2);
        ffma2(acc[2], p1.x, w2); ffma2(acc[3], p1.y, w2);
        ffma2(acc[4], p2.x, w2); ffma2(acc[5], p2.y, w2);
        ffma2(acc[6], p3.x, w2); ffma2(acc[7], p3.y, w2);
    }
    #pragma unroll 4
    for (int j = 0; j < DE; j++) {
        unsigned long long w2 = pk2(Wev[j * DD + c]);
        const ulonglong2* yr = (const ulonglong2*)(yq + (DD + j) * NPB);
        ulonglong2 p0 = yr[0], p1 = yr[1], p2 = yr[2], p3 = yr[3];
        ffma2(acc[0], p0.x, w2); ffma2(acc[1], p0.y, w2);
        ffma2(acc[2], p1.x, w2); ffma2(acc[3], p1.y, w2);
        ffma2(acc[4], p2.x, w2); ffma2(acc[5], p2.y, w2);
        ffma2(acc[6], p3.x, w2); ffma2(acc[7], p3.y, w2);
    }

    float bb = bv[c] + bev[c];
    #pragma unroll
    for (int m = 0; m < 8; m++) {
        float lo, hi;
        asm("mov.b64 {%0, %1}, %2;" : "=f"(lo), "=f"(hi) : "l"(acc[m]));
        out[(size_t)(n0 + 2 * m + 0) * DD + c] = lo + as[2 * m + 0] * bb;
        out[(size_t)(n0 + 2 * m + 1) * DD + c] = hi + as[2 * m + 1] * bb;
    }
}

// ---------------------------------------------------------------------------
extern "C" void kernel_launch(void* const* d_in, const int* in_sizes, int n_in,
                              void* d_out, int out_size) {
    const float* x     = (const float*)d_in[0];
    const int*   ei    = (const int*)d_in[1];
    const float* e_emb = (const float*)d_in[2];
    const int*   bi    = (const int*)d_in[3];

    int wb = 4;
    if (n_in >= 16 && in_sizes[4] <= 1) wb = 5;
    const float* Wq  = (const float*)d_in[wb + 0];
    const float* bq  = (const float*)d_in[wb + 1];
    const float* Wk  = (const float*)d_in[wb + 2];
    const float* bk  = (const float*)d_in[wb + 3];
    const float* Wv  = (const float*)d_in[wb + 4];
    const float* bv  = (const float*)d_in[wb + 5];
    const float* Wew = (const float*)d_in[wb + 6];
    const float* bew = (const float*)d_in[wb + 7];
    const float* Wev = (const float*)d_in[wb + 8];
    const float* bev = (const float*)d_in[wb + 9];
    const float* Wa  = (const float*)d_in[wb + 10];

    float* out = (float*)d_out;

    k_prep<<<2, 256>>>(Wq, Wk, Wew, bq, bk, bew, Wa);
    k_node<<<BN / 8, 256>>>(x);
    k_edge1<<<(EE * 4) / 128, 128>>>(ei, bi, e_emb);
    k_scanA<<<SCAN_NBLK, SCAN_B>>>();
    k_scanB<<<1, SCAN_B>>>();
    k_scanC<<<SCAN_NBLK, SCAN_B>>>();
    k_scatter<<<(EE + 255) / 256, 256>>>(ei, bi);
    k_gather<<<BN / GNPB, 256>>>(x, e_emb);
    k_epi<<<BN / NPB, 128>>>(Wv, bv, Wev, bev, out);
    (void)out_size;
}

// round 12
// speedup vs baseline: 1.2824x; 1.0082x over previous
#include <cuda_runtime.h>
#include <cuda_bf16.h>
#include <math.h>

#define BB 4
#define NN 50000
#define BN 200000          // BB*NN
#define EE 600000
#define DD 128
#define DE 64
#define NPB 16             // nodes per epilogue block
#define GNPB 32            // nodes per gather block
#define CAP 32             // fixed bucket capacity (Poisson(3) max deg << 32)

// ---- scratch: static __device__ arrays only ----
__device__ float4 g_y4[(size_t)BN * 32];   // Σ alpha * x[dst]  per src (102.4 MB)
__device__ float4 g_u4[(size_t)BN * 16];   // Σ alpha * e_emb   per src (51.2 MB)
__device__ float  g_asum[BN];              // Σ alpha           per src
__device__ float  g_attsum[BN];            // Σ exp(logit)      per dst
__device__ float  g_qa[BN];
__device__ float  g_ka[BN];
__device__ float4 g_wqa4[32];
__device__ float4 g_wka4[32];
__device__ float4 g_wea4[16];
__device__ float  g_cb[1];
__device__ unsigned g_cnt[BN];             // per-src bucket fill count
__device__ int4     g_meta[(size_t)BN * CAP];  // {gd, eid, ex_bits, 0} (102.4 MB)

__device__ __forceinline__ void redg(float* p, float v) {
    unsigned long long gp = (unsigned long long)__cvta_generic_to_global(p);
    asm volatile("red.global.add.f32 [%0], %1;" :: "l"(gp), "f"(v) : "memory");
}
__device__ __forceinline__ unsigned long long pk2(float x) {
    unsigned long long r;
    asm("mov.b64 %0, {%1, %1};" : "=l"(r) : "f"(x));
    return r;
}
__device__ __forceinline__ void ffma2(unsigned long long& d, unsigned long long a,
                                      unsigned long long b) {
    asm("fma.rn.f32x2 %0, %1, %2, %0;" : "+l"(d) : "l"(a), "l"(b));
}

// ---------------------------------------------------------------------------
// K0: fold Wa. Thread-per-output, contiguous float4 row reads, 2x256 threads.
// ---------------------------------------------------------------------------
__global__ __launch_bounds__(256) void k_prep(const float* __restrict__ Wq,
                                              const float* __restrict__ Wk,
                                              const float* __restrict__ Wew,
                                              const float* __restrict__ bq,
                                              const float* __restrict__ bk,
                                              const float* __restrict__ bew,
                                              const float* __restrict__ Wa) {
    int j = blockIdx.x * blockDim.x + threadIdx.x;
    const float4* wa4 = (const float4*)Wa;
    if (j < 128) {
        const float4* row = (const float4*)(Wq + (size_t)j * DD);
        float s = 0.f;
        #pragma unroll
        for (int k = 0; k < 32; k++) {
            float4 r = row[k], w = wa4[k];
            s += r.x * w.x + r.y * w.y + r.z * w.z + r.w * w.w;
        }
        ((float*)g_wqa4)[j] = s;
    } else if (j < 256) {
        const float4* row = (const float4*)(Wk + (size_t)(j - 128) * DD);
        float s = 0.f;
        #pragma unroll
        for (int k = 0; k < 32; k++) {
            float4 r = row[k], w = wa4[k];
            s += r.x * w.x + r.y * w.y + r.z * w.z + r.w * w.w;
        }
        ((float*)g_wka4)[j - 128] = s;
    } else if (j < 320) {
        const float4* row = (const float4*)(Wew + (size_t)(j - 256) * DD);
        float s = 0.f;
        #pragma unroll
        for (int k = 0; k < 32; k++) {
            float4 r = row[k], w = wa4[k];
            s += r.x * w.x + r.y * w.y + r.z * w.z + r.w * w.w;
        }
        ((float*)g_wea4)[j - 256] = s;
    } else if (j == 320) {
        float c = 0.f;
        for (int k = 0; k < DD; k++) c += (bq[k] + bk[k] + bew[k]) * Wa[k];
        g_cb[0] = c;
    }
}

// ---------------------------------------------------------------------------
// K1: per-node scalars + fused zeroing (attsum/cnt)
// ---------------------------------------------------------------------------
__global__ __launch_bounds__(256) void k_node(const float* __restrict__ x) {
    int lin = blockIdx.x * blockDim.x + threadIdx.x;
    if (lin < BN) { g_attsum[lin] = 0.f; g_cnt[lin] = 0u; }
    int w = lin >> 5;
    int lane = threadIdx.x & 31;
    if (w >= BN) return;
    float4 xv = ((const float4*)x)[(size_t)w * 32 + lane];
    float4 wq = g_wqa4[lane];
    float4 wk = g_wka4[lane];
    float pq = xv.x * wq.x + xv.y * wq.y + xv.z * wq.z + xv.w * wq.w;
    float pk = xv.x * wk.x + xv.y * wk.y + xv.z * wk.z + xv.w * wk.w;
    #pragma unroll
    for (int o = 16; o > 0; o >>= 1) {
        pq += __shfl_xor_sync(0xffffffffu, pq, o);
        pk += __shfl_xor_sync(0xffffffffu, pk, o);
    }
    if (lane == 0) { g_qa[w] = pq; g_ka[w] = pk; }
}

// ---------------------------------------------------------------------------
// edge pass: logit/exp, attsum reduction, AND direct bucket scatter
// (slot claimed via returning atomic; ex stored, alpha deferred to gather)
// ---------------------------------------------------------------------------
__global__ __launch_bounds__(128) void k_edge1(const int* __restrict__ ei,
                                               const int* __restrict__ bi,
                                               const float* __restrict__ e_emb) {
    int t = blockIdx.x * blockDim.x + threadIdx.x;
    int e = t >> 2;
    int sub = t & 3;
    if (e >= EE) return;
    const float4* er = (const float4*)(e_emb + (size_t)e * DE);
    float p = 0.f;
    #pragma unroll
    for (int i = 0; i < 4; i++) {
        float4 v  = er[sub * 4 + i];
        float4 wv = g_wea4[sub * 4 + i];
        p += v.x * wv.x + v.y * wv.y + v.z * wv.z + v.w * wv.w;
    }
    p += __shfl_xor_sync(0xffffffffu, p, 1);
    p += __shfl_xor_sync(0xffffffffu, p, 2);
    if (sub == 0) {
        int s = ei[e];
        int d = ei[EE + e];
        int b = bi[e];
        int gs = b * NN + s;
        int gd = b * NN + d;
        float logit = (g_qa[gs] + g_ka[gd] + p + g_cb[0]) * 0.25f;
        float ex = expf(logit);
        redg(&g_attsum[gd], ex);
        unsigned idx = atomicAdd(&g_cnt[gs], 1u);
        g_meta[(size_t)gs * CAP + idx] = make_int4(gd, e, __float_as_int(ex), 0);
    }
}

// ---------------------------------------------------------------------------
// gather: one warp per src node x 4. Bucket addresses are STATIC (gs*CAP+k)
// so meta/attsum/x/e loads form just two dependent epochs. Dummy slots have
// ex=0 -> alpha=0 (no branches).
// ---------------------------------------------------------------------------
__global__ __launch_bounds__(256) void k_gather(const float* __restrict__ x,
                                                const float* __restrict__ e_emb) {
    __shared__ unsigned scnt[GNPB];
    int t = threadIdx.x;
    int gs0 = blockIdx.x * GNPB;
    if (t < GNPB) scnt[t] = g_cnt[gs0 + t];
    __syncthreads();

    int w = t >> 5, lane = t & 31;
    const int4 mz = make_int4(0, 0, 0, 0);

    #pragma unroll
    for (int nn = 0; nn < 4; nn++) {
        int li = w * 4 + nn;
        int gs = gs0 + li;
        unsigned deg = scnt[li];
        const int4* mrow = g_meta + (size_t)gs * CAP;

        float4 ya = make_float4(0.f, 0.f, 0.f, 0.f);
        float4 ua = make_float4(0.f, 0.f, 0.f, 0.f);
        float asum = 0.f;

        for (unsigned p = 0; p < deg; p += 4) {
            int4 m0 = mrow[p];
            int4 m1 = (p + 1 < deg) ? mrow[p + 1] : mz;
            int4 m2 = (p + 2 < deg) ? mrow[p + 2] : mz;
            int4 m3 = (p + 3 < deg) ? mrow[p + 3] : mz;

            float s0 = g_attsum[m0.x];
            float s1 = g_attsum[m1.x];
            float s2 = g_attsum[m2.x];
            float s3 = g_attsum[m3.x];
            float a0 = __fdividef(__int_as_float(m0.z), s0 + 1e-9f);
            float a1 = __fdividef(__int_as_float(m1.z), s1 + 1e-9f);
            float a2 = __fdividef(__int_as_float(m2.z), s2 + 1e-9f);
            float a3 = __fdividef(__int_as_float(m3.z), s3 + 1e-9f);

            float4 x0 = ((const float4*)x)[(size_t)m0.x * 32 + lane];
            float4 x1 = ((const float4*)x)[(size_t)m1.x * 32 + lane];
            float4 x2 = ((const float4*)x)[(size_t)m2.x * 32 + lane];
            float4 x3 = ((const float4*)x)[(size_t)m3.x * 32 + lane];

            if (lane < 16) {
                float4 e0 = __ldcs((const float4*)e_emb + (size_t)m0.y * 16 + lane);
                float4 e1 = __ldcs((const float4*)e_emb + (size_t)m1.y * 16 + lane);
                float4 e2 = __ldcs((const float4*)e_emb + (size_t)m2.y * 16 + lane);
                float4 e3 = __ldcs((const float4*)e_emb + (size_t)m3.y * 16 + lane);
                ua.x += a0 * e0.x + a1 * e1.x + a2 * e2.x + a3 * e3.x;
                ua.y += a0 * e0.y + a1 * e1.y + a2 * e2.y + a3 * e3.y;
                ua.z += a0 * e0.z + a1 * e1.z + a2 * e2.z + a3 * e3.z;
                ua.w += a0 * e0.w + a1 * e1.w + a2 * e2.w + a3 * e3.w;
            }

            ya.x += a0 * x0.x + a1 * x1.x + a2 * x2.x + a3 * x3.x;
            ya.y += a0 * x0.y + a1 * x1.y + a2 * x2.y + a3 * x3.y;
            ya.z += a0 * x0.z + a1 * x1.z + a2 * x2.z + a3 * x3.z;
            ya.w += a0 * x0.w + a1 * x1.w + a2 * x2.w + a3 * x3.w;
            asum += a0 + a1 + a2 + a3;
        }
        g_y4[(size_t)gs * 32 + lane] = ya;
        if (lane < 16) g_u4[(size_t)gs * 16 + lane] = ua;
        if (lane == 0) g_asum[gs] = asum;
    }
}

// ---------------------------------------------------------------------------
// epilogue — R7-proven: NPB=16 nodes / 128-thread block, transposed smem,
// f32x2 FMA, weights from global (L1-resident across CTAs).
// ---------------------------------------------------------------------------
__global__ __launch_bounds__(128) void k_epi(const float* __restrict__ Wv,
                                             const float* __restrict__ bv,
                                             const float* __restrict__ Wev,
                                             const float* __restrict__ bev,
                                             float* __restrict__ out) {
    __shared__ __align__(16) float yq[(DD + DE) * NPB];
    __shared__ float as[NPB];
    int t = threadIdx.x;
    int n0 = blockIdx.x * NPB;

    {
        int i = t & 15, g = t >> 4;
        const float4* yrow = g_y4 + (size_t)(n0 + i) * 32 + g * 4;
        #pragma unroll
        for (int q = 0; q < 4; q++) {
            float4 v = yrow[q];
            int j = g * 16 + q * 4;
            yq[(j + 0) * NPB + i] = v.x;
            yq[(j + 1) * NPB + i] = v.y;
            yq[(j + 2) * NPB + i] = v.z;
            yq[(j + 3) * NPB + i] = v.w;
        }
        const float4* urow = g_u4 + (size_t)(n0 + i) * 16 + g * 2;
        #pragma unroll
        for (int q = 0; q < 2; q++) {
            float4 v = urow[q];
            int j = DD + g * 8 + q * 4;
            yq[(j + 0) * NPB + i] = v.x;
            yq[(j + 1) * NPB + i] = v.y;
            yq[(j + 2) * NPB + i] = v.z;
            yq[(j + 3) * NPB + i] = v.w;
        }
        if (t < NPB) as[t] = g_asum[n0 + t];
    }
    __syncthreads();

    int c = t;
    unsigned long long acc[8] = {0, 0, 0, 0, 0, 0, 0, 0};

    #pragma unroll 4
    for (int j = 0; j < DD; j++) {
        unsigned long long w2 = pk2(Wv[j * DD + c]);
        const ulonglong2* yr = (const ulonglong2*)(yq + j * NPB);
        ulonglong2 p0 = yr[0], p1 = yr[1], p2 = yr[2], p3 = yr[3];
        ffma2(acc[0], p0.x, w2); ffma2(acc[1], p0.y, w2);
        ffma2(acc[2], p1.x, w2); ffma2(acc[3], p1.y, w2);
        ffma2(acc[4], p2.x, w2); ffma2(acc[5], p2.y, w2);
        ffma2(acc[6], p3.x, w2); ffma2(acc[7], p3.y, w2);
    }
    #pragma unroll 4
    for (int j = 0; j < DE; j++) {
        unsigned long long w2 = pk2(Wev[j * DD + c]);
        const ulonglong2* yr = (const ulonglong2*)(yq + (DD + j) * NPB);
        ulonglong2 p0 = yr[0], p1 = yr[1], p2 = yr[2], p3 = yr[3];
        ffma2(acc[0], p0.x, w2); ffma2(acc[1], p0.y, w2);
        ffma2(acc[2], p1.x, w2); ffma2(acc[3], p1.y, w2);
        ffma2(acc[4], p2.x, w2); ffma2(acc[5], p2.y, w2);
        ffma2(acc[6], p3.x, w2); ffma2(acc[7], p3.y, w2);
    }

    float bb = bv[c] + bev[c];
    #pragma unroll
    for (int m = 0; m < 8; m++) {
        float lo, hi;
        asm("mov.b64 {%0, %1}, %2;" : "=f"(lo), "=f"(hi) : "l"(acc[m]));
        out[(size_t)(n0 + 2 * m + 0) * DD + c] = lo + as[2 * m + 0] * bb;
        out[(size_t)(n0 + 2 * m + 1) * DD + c] = hi + as[2 * m + 1] * bb;
    }
}

// ---------------------------------------------------------------------------
extern "C" void kernel_launch(void* const* d_in, const int* in_sizes, int n_in,
                              void* d_out, int out_size) {
    const float* x     = (const float*)d_in[0];
    const int*   ei    = (const int*)d_in[1];
    const float* e_emb = (const float*)d_in[2];
    const int*   bi    = (const int*)d_in[3];

    int wb = 4;
    if (n_in >= 16 && in_sizes[4] <= 1) wb = 5;
    const float* Wq  = (const float*)d_in[wb + 0];
    const float* bq  = (const float*)d_in[wb + 1];
    const float* Wk  = (const float*)d_in[wb + 2];
    const float* bk  = (const float*)d_in[wb + 3];
    const float* Wv  = (const float*)d_in[wb + 4];
    const float* bv  = (const float*)d_in[wb + 5];
    const float* Wew = (const float*)d_in[wb + 6];
    const float* bew = (const float*)d_in[wb + 7];
    const float* Wev = (const float*)d_in[wb + 8];
    const float* bev = (const float*)d_in[wb + 9];
    const float* Wa  = (const float*)d_in[wb + 10];

    float* out = (float*)d_out;

    k_prep<<<2, 256>>>(Wq, Wk, Wew, bq, bk, bew, Wa);
    k_node<<<BN / 8, 256>>>(x);
    k_edge1<<<(EE * 4) / 128, 128>>>(ei, bi, e_emb);
    k_gather<<<BN / GNPB, 256>>>(x, e_emb);
    k_epi<<<BN / NPB, 128>>>(Wv, bv, Wev, bev, out);
    (void)out_size;
}

// round 13
// speedup vs baseline: 1.5169x; 1.1829x over previous
#include <cuda_runtime.h>
#include <cuda_bf16.h>
#include <math.h>

#define BB 4
#define NN 50000
#define BN 200000          // BB*NN
#define EE 600000
#define DD 128
#define DE 64
#define NPB 16             // nodes per fused block
#define CAP 32             // fixed bucket capacity (Poisson(3) max deg << 32)
#define NMS 196            // node-major smem stride (floats), 16B-aligned, bank-skewed

// ---- scratch: static __device__ arrays only ----
__device__ float  g_attsum[BN];            // Σ exp(logit)      per dst
__device__ float  g_qa[BN];
__device__ float  g_ka[BN];
__device__ float4 g_wqa4[32];
__device__ float4 g_wka4[32];
__device__ float4 g_wea4[16];
__device__ float  g_cb[1];
__device__ unsigned g_cnt[BN];             // per-src bucket fill count
__device__ int4     g_meta[(size_t)BN * CAP];  // {gd, eid, ex_bits, 0}

__device__ __forceinline__ void redg(float* p, float v) {
    unsigned long long gp = (unsigned long long)__cvta_generic_to_global(p);
    asm volatile("red.global.add.f32 [%0], %1;" :: "l"(gp), "f"(v) : "memory");
}
__device__ __forceinline__ unsigned long long pk2(float x) {
    unsigned long long r;
    asm("mov.b64 %0, {%1, %1};" : "=l"(r) : "f"(x));
    return r;
}
__device__ __forceinline__ void ffma2(unsigned long long& d, unsigned long long a,
                                      unsigned long long b) {
    asm("fma.rn.f32x2 %0, %1, %2, %0;" : "+l"(d) : "l"(a), "l"(b));
}

// ---------------------------------------------------------------------------
// K0: fold Wa. Thread-per-output, contiguous float4 row reads, 2x256 threads.
// ---------------------------------------------------------------------------
__global__ __launch_bounds__(256) void k_prep(const float* __restrict__ Wq,
                                              const float* __restrict__ Wk,
                                              const float* __restrict__ Wew,
                                              const float* __restrict__ bq,
                                              const float* __restrict__ bk,
                                              const float* __restrict__ bew,
                                              const float* __restrict__ Wa) {
    int j = blockIdx.x * blockDim.x + threadIdx.x;
    const float4* wa4 = (const float4*)Wa;
    if (j < 128) {
        const float4* row = (const float4*)(Wq + (size_t)j * DD);
        float s = 0.f;
        #pragma unroll
        for (int k = 0; k < 32; k++) {
            float4 r = row[k], w = wa4[k];
            s += r.x * w.x + r.y * w.y + r.z * w.z + r.w * w.w;
        }
        ((float*)g_wqa4)[j] = s;
    } else if (j < 256) {
        const float4* row = (const float4*)(Wk + (size_t)(j - 128) * DD);
        float s = 0.f;
        #pragma unroll
        for (int k = 0; k < 32; k++) {
            float4 r = row[k], w = wa4[k];
            s += r.x * w.x + r.y * w.y + r.z * w.z + r.w * w.w;
        }
        ((float*)g_wka4)[j - 128] = s;
    } else if (j < 320) {
        const float4* row = (const float4*)(Wew + (size_t)(j - 256) * DD);
        float s = 0.f;
        #pragma unroll
        for (int k = 0; k < 32; k++) {
            float4 r = row[k], w = wa4[k];
            s += r.x * w.x + r.y * w.y + r.z * w.z + r.w * w.w;
        }
        ((float*)g_wea4)[j - 256] = s;
    } else if (j == 320) {
        float c = 0.f;
        for (int k = 0; k < DD; k++) c += (bq[k] + bk[k] + bew[k]) * Wa[k];
        g_cb[0] = c;
    }
}

// ---------------------------------------------------------------------------
// K1: per-node scalars + fused zeroing (attsum/cnt)
// ---------------------------------------------------------------------------
__global__ __launch_bounds__(256) void k_node(const float* __restrict__ x) {
    int lin = blockIdx.x * blockDim.x + threadIdx.x;
    if (lin < BN) { g_attsum[lin] = 0.f; g_cnt[lin] = 0u; }
    int w = lin >> 5;
    int lane = threadIdx.x & 31;
    if (w >= BN) return;
    float4 xv = ((const float4*)x)[(size_t)w * 32 + lane];
    float4 wq = g_wqa4[lane];
    float4 wk = g_wka4[lane];
    float pq = xv.x * wq.x + xv.y * wq.y + xv.z * wq.z + xv.w * wq.w;
    float pk = xv.x * wk.x + xv.y * wk.y + xv.z * wk.z + xv.w * wk.w;
    #pragma unroll
    for (int o = 16; o > 0; o >>= 1) {
        pq += __shfl_xor_sync(0xffffffffu, pq, o);
        pk += __shfl_xor_sync(0xffffffffu, pk, o);
    }
    if (lane == 0) { g_qa[w] = pq; g_ka[w] = pk; }
}

// ---------------------------------------------------------------------------
// edge pass: logit/exp, attsum reduction, direct bucket scatter
// ---------------------------------------------------------------------------
__global__ __launch_bounds__(128) void k_edge1(const int* __restrict__ ei,
                                               const int* __restrict__ bi,
                                               const float* __restrict__ e_emb) {
    int t = blockIdx.x * blockDim.x + threadIdx.x;
    int e = t >> 2;
    int sub = t & 3;
    if (e >= EE) return;
    const float4* er = (const float4*)(e_emb + (size_t)e * DE);
    float p = 0.f;
    #pragma unroll
    for (int i = 0; i < 4; i++) {
        float4 v  = er[sub * 4 + i];
        float4 wv = g_wea4[sub * 4 + i];
        p += v.x * wv.x + v.y * wv.y + v.z * wv.z + v.w * wv.w;
    }
    p += __shfl_xor_sync(0xffffffffu, p, 1);
    p += __shfl_xor_sync(0xffffffffu, p, 2);
    if (sub == 0) {
        int s = ei[e];
        int d = ei[EE + e];
        int b = bi[e];
        int gs = b * NN + s;
        int gd = b * NN + d;
        float logit = (g_qa[gs] + g_ka[gd] + p + g_cb[0]) * 0.25f;
        float ex = expf(logit);
        redg(&g_attsum[gd], ex);
        unsigned idx = atomicAdd(&g_cnt[gs], 1u);
        g_meta[(size_t)gs * CAP + idx] = make_int4(gd, e, __float_as_int(ex), 0);
    }
}

// ---------------------------------------------------------------------------
// FUSED gather + epilogue: 128 threads / 16 nodes.
//   Phase 1: 4 warps x 4 nodes — batch-4 bucket gather -> node-major smem.
//   Phase 2: in-block transpose -> yq[j][16] layout.
//   Phase 3: proven FFMA2 epilogue (weights from global, L1-resident).
// No y/u global round-trip.
// ---------------------------------------------------------------------------
__global__ __launch_bounds__(128) void k_fused(const float* __restrict__ x,
                                               const float* __restrict__ e_emb,
                                               const float* __restrict__ Wv,
                                               const float* __restrict__ bv,
                                               const float* __restrict__ Wev,
                                               const float* __restrict__ bev,
                                               float* __restrict__ out) {
    __shared__ __align__(16) float ynm[NPB * NMS];       // node-major y(0..127)+u(128..191)
    __shared__ __align__(16) float yq[(DD + DE) * NPB];  // transposed for epi
    __shared__ float as[NPB];
    int t = threadIdx.x;
    int n0 = blockIdx.x * NPB;
    int w = t >> 5, lane = t & 31;

    // ---- Phase 1: gather (verbatim R12 inner loop, output to smem) ----
    {
        const int4 mz = make_int4(0, 0, 0, 0);
        #pragma unroll
        for (int nn = 0; nn < 4; nn++) {
            int li = w * 4 + nn;
            int gs = n0 + li;
            unsigned deg = g_cnt[gs];
            const int4* mrow = g_meta + (size_t)gs * CAP;

            float4 ya = make_float4(0.f, 0.f, 0.f, 0.f);
            float4 ua = make_float4(0.f, 0.f, 0.f, 0.f);
            float asum = 0.f;

            for (unsigned p = 0; p < deg; p += 4) {
                int4 m0 = mrow[p];
                int4 m1 = (p + 1 < deg) ? mrow[p + 1] : mz;
                int4 m2 = (p + 2 < deg) ? mrow[p + 2] : mz;
                int4 m3 = (p + 3 < deg) ? mrow[p + 3] : mz;

                float s0 = g_attsum[m0.x];
                float s1 = g_attsum[m1.x];
                float s2 = g_attsum[m2.x];
                float s3 = g_attsum[m3.x];
                float a0 = __fdividef(__int_as_float(m0.z), s0 + 1e-9f);
                float a1 = __fdividef(__int_as_float(m1.z), s1 + 1e-9f);
                float a2 = __fdividef(__int_as_float(m2.z), s2 + 1e-9f);
                float a3 = __fdividef(__int_as_float(m3.z), s3 + 1e-9f);

                float4 x0 = ((const float4*)x)[(size_t)m0.x * 32 + lane];
                float4 x1 = ((const float4*)x)[(size_t)m1.x * 32 + lane];
                float4 x2 = ((const float4*)x)[(size_t)m2.x * 32 + lane];
                float4 x3 = ((const float4*)x)[(size_t)m3.x * 32 + lane];

                if (lane < 16) {
                    float4 e0 = __ldcs((const float4*)e_emb + (size_t)m0.y * 16 + lane);
                    float4 e1 = __ldcs((const float4*)e_emb + (size_t)m1.y * 16 + lane);
                    float4 e2 = __ldcs((const float4*)e_emb + (size_t)m2.y * 16 + lane);
                    float4 e3 = __ldcs((const float4*)e_emb + (size_t)m3.y * 16 + lane);
                    ua.x += a0 * e0.x + a1 * e1.x + a2 * e2.x + a3 * e3.x;
                    ua.y += a0 * e0.y + a1 * e1.y + a2 * e2.y + a3 * e3.y;
                    ua.z += a0 * e0.z + a1 * e1.z + a2 * e2.z + a3 * e3.z;
                    ua.w += a0 * e0.w + a1 * e1.w + a2 * e2.w + a3 * e3.w;
                }

                ya.x += a0 * x0.x + a1 * x1.x + a2 * x2.x + a3 * x3.x;
                ya.y += a0 * x0.y + a1 * x1.y + a2 * x2.y + a3 * x3.y;
                ya.z += a0 * x0.z + a1 * x1.z + a2 * x2.z + a3 * x3.z;
                ya.w += a0 * x0.w + a1 * x1.w + a2 * x2.w + a3 * x3.w;
                asum += a0 + a1 + a2 + a3;
            }
            // node-major smem stores (v4, conflict-free: stride NMS=196)
            *(float4*)(ynm + li * NMS + 4 * lane) = ya;
            if (lane < 16)
                *(float4*)(ynm + li * NMS + DD + 4 * lane) = ua;
            if (lane == 0) as[li] = asum;
        }
    }
    __syncthreads();

    // ---- Phase 2: transpose ynm -> yq (epi's proven layouts) ----
    {
        int i = t & 15, g = t >> 4;
        #pragma unroll
        for (int q = 0; q < 4; q++) {
            float4 v = *(const float4*)(ynm + i * NMS + g * 16 + q * 4);
            int j = g * 16 + q * 4;
            yq[(j + 0) * NPB + i] = v.x;
            yq[(j + 1) * NPB + i] = v.y;
            yq[(j + 2) * NPB + i] = v.z;
            yq[(j + 3) * NPB + i] = v.w;
        }
        #pragma unroll
        for (int q = 0; q < 2; q++) {
            float4 v = *(const float4*)(ynm + i * NMS + DD + g * 8 + q * 4);
            int j = DD + g * 8 + q * 4;
            yq[(j + 0) * NPB + i] = v.x;
            yq[(j + 1) * NPB + i] = v.y;
            yq[(j + 2) * NPB + i] = v.z;
            yq[(j + 3) * NPB + i] = v.w;
        }
    }
    __syncthreads();

    // ---- Phase 3: epilogue compute (verbatim R12) ----
    int c = t;
    unsigned long long acc[8] = {0, 0, 0, 0, 0, 0, 0, 0};

    #pragma unroll 4
    for (int j = 0; j < DD; j++) {
        unsigned long long w2 = pk2(Wv[j * DD + c]);
        const ulonglong2* yr = (const ulonglong2*)(yq + j * NPB);
        ulonglong2 p0 = yr[0], p1 = yr[1], p2 = yr[2], p3 = yr[3];
        ffma2(acc[0], p0.x, w2); ffma2(acc[1], p0.y, w2);
        ffma2(acc[2], p1.x, w2); ffma2(acc[3], p1.y, w2);
        ffma2(acc[4], p2.x, w2); ffma2(acc[5], p2.y, w2);
        ffma2(acc[6], p3.x, w2); ffma2(acc[7], p3.y, w2);
    }
    #pragma unroll 4
    for (int j = 0; j < DE; j++) {
        unsigned long long w2 = pk2(Wev[j * DD + c]);
        const ulonglong2* yr = (const ulonglong2*)(yq + (DD + j) * NPB);
        ulonglong2 p0 = yr[0], p1 = yr[1], p2 = yr[2], p3 = yr[3];
        ffma2(acc[0], p0.x, w2); ffma2(acc[1], p0.y, w2);
        ffma2(acc[2], p1.x, w2); ffma2(acc[3], p1.y, w2);
        ffma2(acc[4], p2.x, w2); ffma2(acc[5], p2.y, w2);
        ffma2(acc[6], p3.x, w2); ffma2(acc[7], p3.y, w2);
    }

    float bb = bv[c] + bev[c];
    #pragma unroll
    for (int m = 0; m < 8; m++) {
        float lo, hi;
        asm("mov.b64 {%0, %1}, %2;" : "=f"(lo), "=f"(hi) : "l"(acc[m]));
        out[(size_t)(n0 + 2 * m + 0) * DD + c] = lo + as[2 * m + 0] * bb;
        out[(size_t)(n0 + 2 * m + 1) * DD + c] = hi + as[2 * m + 1] * bb;
    }
}

// ---------------------------------------------------------------------------
extern "C" void kernel_launch(void* const* d_in, const int* in_sizes, int n_in,
                              void* d_out, int out_size) {
    const float* x     = (const float*)d_in[0];
    const int*   ei    = (const int*)d_in[1];
    const float* e_emb = (const float*)d_in[2];
    const int*   bi    = (const int*)d_in[3];

    int wb = 4;
    if (n_in >= 16 && in_sizes[4] <= 1) wb = 5;
    const float* Wq  = (const float*)d_in[wb + 0];
    const float* bq  = (const float*)d_in[wb + 1];
    const float* Wk  = (const float*)d_in[wb + 2];
    const float* bk  = (const float*)d_in[wb + 3];
    const float* Wv  = (const float*)d_in[wb + 4];
    const float* bv  = (const float*)d_in[wb + 5];
    const float* Wew = (const float*)d_in[wb + 6];
    const float* bew = (const float*)d_in[wb + 7];
    const float* Wev = (const float*)d_in[wb + 8];
    const float* bev = (const float*)d_in[wb + 9];
    const float* Wa  = (const float*)d_in[wb + 10];

    float* out = (float*)d_out;

    k_prep<<<2, 256>>>(Wq, Wk, Wew, bq, bk, bew, Wa);
    k_node<<<BN / 8, 256>>>(x);
    k_edge1<<<(EE * 4) / 128, 128>>>(ei, bi, e_emb);
    k_fused<<<BN / NPB, 128>>>(x, e_emb, Wv, bv, Wev, bev, out);
    (void)out_size;
}

// round 14
// speedup vs baseline: 1.5752x; 1.0384x over previous
#include <cuda_runtime.h>
#include <cuda_bf16.h>
#include <math.h>

#define BB 4
#define NN 50000
#define BN 200000          // BB*NN
#define EE 600000
#define DD 128
#define DE 64
#define NPB 32             // nodes per fused block
#define CAP 32             // fixed bucket capacity (Poisson(3) max deg << 32)
#define NMS 196            // node-major smem stride (floats)

// ---- scratch: static __device__ arrays only ----
__device__ float  g_attsum[BN];            // Σ exp(logit)      per dst
__device__ float  g_qa[BN];
__device__ float  g_ka[BN];
__device__ float4 g_wqa4[32];
__device__ float4 g_wka4[32];
__device__ float4 g_wea4[16];
__device__ float  g_cb[1];
__device__ unsigned g_cnt[BN];             // per-src bucket fill count
__device__ int4     g_meta[(size_t)BN * CAP];  // {gd, eid, ex_bits, 0}

__device__ __forceinline__ void redg(float* p, float v) {
    unsigned long long gp = (unsigned long long)__cvta_generic_to_global(p);
    asm volatile("red.global.add.f32 [%0], %1;" :: "l"(gp), "f"(v) : "memory");
}
__device__ __forceinline__ unsigned long long pk2(float x) {
    unsigned long long r;
    asm("mov.b64 %0, {%1, %1};" : "=l"(r) : "f"(x));
    return r;
}
__device__ __forceinline__ void ffma2(unsigned long long& d, unsigned long long a,
                                      unsigned long long b) {
    asm("fma.rn.f32x2 %0, %1, %2, %0;" : "+l"(d) : "l"(a), "l"(b));
}

// ---------------------------------------------------------------------------
// K0: fold Wa. Thread-per-output, contiguous float4 row reads, 2x256 threads.
// ---------------------------------------------------------------------------
__global__ __launch_bounds__(256) void k_prep(const float* __restrict__ Wq,
                                              const float* __restrict__ Wk,
                                              const float* __restrict__ Wew,
                                              const float* __restrict__ bq,
                                              const float* __restrict__ bk,
                                              const float* __restrict__ bew,
                                              const float* __restrict__ Wa) {
    int j = blockIdx.x * blockDim.x + threadIdx.x;
    const float4* wa4 = (const float4*)Wa;
    if (j < 128) {
        const float4* row = (const float4*)(Wq + (size_t)j * DD);
        float s = 0.f;
        #pragma unroll
        for (int k = 0; k < 32; k++) {
            float4 r = row[k], w = wa4[k];
            s += r.x * w.x + r.y * w.y + r.z * w.z + r.w * w.w;
        }
        ((float*)g_wqa4)[j] = s;
    } else if (j < 256) {
        const float4* row = (const float4*)(Wk + (size_t)(j - 128) * DD);
        float s = 0.f;
        #pragma unroll
        for (int k = 0; k < 32; k++) {
            float4 r = row[k], w = wa4[k];
            s += r.x * w.x + r.y * w.y + r.z * w.z + r.w * w.w;
        }
        ((float*)g_wka4)[j - 128] = s;
    } else if (j < 320) {
        const float4* row = (const float4*)(Wew + (size_t)(j - 256) * DD);
        float s = 0.f;
        #pragma unroll
        for (int k = 0; k < 32; k++) {
            float4 r = row[k], w = wa4[k];
            s += r.x * w.x + r.y * w.y + r.z * w.z + r.w * w.w;
        }
        ((float*)g_wea4)[j - 256] = s;
    } else if (j == 320) {
        float c = 0.f;
        for (int k = 0; k < DD; k++) c += (bq[k] + bk[k] + bew[k]) * Wa[k];
        g_cb[0] = c;
    }
}

// ---------------------------------------------------------------------------
// K1: per-node scalars + fused zeroing (attsum/cnt)
// ---------------------------------------------------------------------------
__global__ __launch_bounds__(256) void k_node(const float* __restrict__ x) {
    int lin = blockIdx.x * blockDim.x + threadIdx.x;
    if (lin < BN) { g_attsum[lin] = 0.f; g_cnt[lin] = 0u; }
    int w = lin >> 5;
    int lane = threadIdx.x & 31;
    if (w >= BN) return;
    float4 xv = ((const float4*)x)[(size_t)w * 32 + lane];
    float4 wq = g_wqa4[lane];
    float4 wk = g_wka4[lane];
    float pq = xv.x * wq.x + xv.y * wq.y + xv.z * wq.z + xv.w * wq.w;
    float pk = xv.x * wk.x + xv.y * wk.y + xv.z * wk.z + xv.w * wk.w;
    #pragma unroll
    for (int o = 16; o > 0; o >>= 1) {
        pq += __shfl_xor_sync(0xffffffffu, pq, o);
        pk += __shfl_xor_sync(0xffffffffu, pk, o);
    }
    if (lane == 0) { g_qa[w] = pq; g_ka[w] = pk; }
}

// ---------------------------------------------------------------------------
// edge pass: logit/exp, attsum reduction, direct bucket scatter
// ---------------------------------------------------------------------------
__global__ __launch_bounds__(128) void k_edge1(const int* __restrict__ ei,
                                               const int* __restrict__ bi,
                                               const float* __restrict__ e_emb) {
    int t = blockIdx.x * blockDim.x + threadIdx.x;
    int e = t >> 2;
    int sub = t & 3;
    if (e >= EE) return;
    const float4* er = (const float4*)(e_emb + (size_t)e * DE);
    float p = 0.f;
    #pragma unroll
    for (int i = 0; i < 4; i++) {
        float4 v  = er[sub * 4 + i];
        float4 wv = g_wea4[sub * 4 + i];
        p += v.x * wv.x + v.y * wv.y + v.z * wv.z + v.w * wv.w;
    }
    p += __shfl_xor_sync(0xffffffffu, p, 1);
    p += __shfl_xor_sync(0xffffffffu, p, 2);
    if (sub == 0) {
        int s = ei[e];
        int d = ei[EE + e];
        int b = bi[e];
        int gs = b * NN + s;
        int gd = b * NN + d;
        float logit = (g_qa[gs] + g_ka[gd] + p + g_cb[0]) * 0.25f;
        float ex = expf(logit);
        redg(&g_attsum[gd], ex);
        unsigned idx = atomicAdd(&g_cnt[gs], 1u);
        g_meta[(size_t)gs * CAP + idx] = make_int4(gd, e, __float_as_int(ex), 0);
    }
}

// ---------------------------------------------------------------------------
// FUSED gather + epilogue v2: 128 threads / 32 nodes.
//   Phase 1: 4 warps x 8 nodes — batch-4 bucket gather -> node-major smem.
//   Phase 2: transpose -> yq[j][32].
//   Phase 3: FFMA2 epilogue, 2 columns per thread (c, c+64), node-half per
//            warp-pair — LDS reuse across columns cuts L1 wavefronts 40%.
// ---------------------------------------------------------------------------
__global__ __launch_bounds__(128) void k_fused(const float* __restrict__ x,
                                               const float* __restrict__ e_emb,
                                               const float* __restrict__ Wv,
                                               const float* __restrict__ bv,
                                               const float* __restrict__ Wev,
                                               const float* __restrict__ bev,
                                               float* __restrict__ out) {
    __shared__ __align__(16) float ynm[NPB * NMS];       // 25,088 B
    __shared__ __align__(16) float yq[(DD + DE) * NPB];  // 24,576 B
    __shared__ float as[NPB];
    int t = threadIdx.x;
    int n0 = blockIdx.x * NPB;
    int w = t >> 5, lane = t & 31;

    // ---- Phase 1: gather (proven batch-4 loop), 8 nodes per warp ----
    {
        const int4 mz = make_int4(0, 0, 0, 0);
        #pragma unroll
        for (int nn = 0; nn < 8; nn++) {
            int li = w * 8 + nn;
            int gs = n0 + li;
            unsigned deg = g_cnt[gs];
            const int4* mrow = g_meta + (size_t)gs * CAP;

            float4 ya = make_float4(0.f, 0.f, 0.f, 0.f);
            float4 ua = make_float4(0.f, 0.f, 0.f, 0.f);
            float asum = 0.f;

            for (unsigned p = 0; p < deg; p += 4) {
                int4 m0 = mrow[p];
                int4 m1 = (p + 1 < deg) ? mrow[p + 1] : mz;
                int4 m2 = (p + 2 < deg) ? mrow[p + 2] : mz;
                int4 m3 = (p + 3 < deg) ? mrow[p + 3] : mz;

                float s0 = g_attsum[m0.x];
                float s1 = g_attsum[m1.x];
                float s2 = g_attsum[m2.x];
                float s3 = g_attsum[m3.x];
                float a0 = __fdividef(__int_as_float(m0.z), s0 + 1e-9f);
                float a1 = __fdividef(__int_as_float(m1.z), s1 + 1e-9f);
                float a2 = __fdividef(__int_as_float(m2.z), s2 + 1e-9f);
                float a3 = __fdividef(__int_as_float(m3.z), s3 + 1e-9f);

                float4 x0 = ((const float4*)x)[(size_t)m0.x * 32 + lane];
                float4 x1 = ((const float4*)x)[(size_t)m1.x * 32 + lane];
                float4 x2 = ((const float4*)x)[(size_t)m2.x * 32 + lane];
                float4 x3 = ((const float4*)x)[(size_t)m3.x * 32 + lane];

                if (lane < 16) {
                    float4 e0 = __ldcs((const float4*)e_emb + (size_t)m0.y * 16 + lane);
                    float4 e1 = __ldcs((const float4*)e_emb + (size_t)m1.y * 16 + lane);
                    float4 e2 = __ldcs((const float4*)e_emb + (size_t)m2.y * 16 + lane);
                    float4 e3 = __ldcs((const float4*)e_emb + (size_t)m3.y * 16 + lane);
                    ua.x += a0 * e0.x + a1 * e1.x + a2 * e2.x + a3 * e3.x;
                    ua.y += a0 * e0.y + a1 * e1.y + a2 * e2.y + a3 * e3.y;
                    ua.z += a0 * e0.z + a1 * e1.z + a2 * e2.z + a3 * e3.z;
                    ua.w += a0 * e0.w + a1 * e1.w + a2 * e2.w + a3 * e3.w;
                }

                ya.x += a0 * x0.x + a1 * x1.x + a2 * x2.x + a3 * x3.x;
                ya.y += a0 * x0.y + a1 * x1.y + a2 * x2.y + a3 * x3.y;
                ya.z += a0 * x0.z + a1 * x1.z + a2 * x2.z + a3 * x3.z;
                ya.w += a0 * x0.w + a1 * x1.w + a2 * x2.w + a3 * x3.w;
                asum += a0 + a1 + a2 + a3;
            }
            *(float4*)(ynm + li * NMS + 4 * lane) = ya;
            if (lane < 16)
                *(float4*)(ynm + li * NMS + DD + 4 * lane) = ua;
            if (lane == 0) as[li] = asum;
        }
    }
    __syncthreads();

    // ---- Phase 2: transpose ynm -> yq[j][32] ----
    {
        int i = t & 31, g = t >> 5;     // node i, chunk g in 0..3
        #pragma unroll
        for (int q = 0; q < 8; q++) {
            float4 v = *(const float4*)(ynm + i * NMS + g * 32 + q * 4);
            int j = g * 32 + q * 4;
            yq[(j + 0) * NPB + i] = v.x;
            yq[(j + 1) * NPB + i] = v.y;
            yq[(j + 2) * NPB + i] = v.z;
            yq[(j + 3) * NPB + i] = v.w;
        }
        #pragma unroll
        for (int q = 0; q < 4; q++) {
            float4 v = *(const float4*)(ynm + i * NMS + DD + g * 16 + q * 4);
            int j = DD + g * 16 + q * 4;
            yq[(j + 0) * NPB + i] = v.x;
            yq[(j + 1) * NPB + i] = v.y;
            yq[(j + 2) * NPB + i] = v.z;
            yq[(j + 3) * NPB + i] = v.w;
        }
    }
    __syncthreads();

    // ---- Phase 3: epilogue — 2 cols/thread, node-half per warp-pair ----
    int c = t & 63;                 // column base (second col = c+64)
    int h = t >> 6;                 // node half: 0 or 1
    int ib = h * 16;
    unsigned long long acc0[8] = {0, 0, 0, 0, 0, 0, 0, 0};
    unsigned long long acc1[8] = {0, 0, 0, 0, 0, 0, 0, 0};

    #pragma unroll 4
    for (int j = 0; j < DD; j++) {
        unsigned long long w20 = pk2(Wv[j * DD + c]);
        unsigned long long w21 = pk2(Wv[j * DD + c + 64]);
        const ulonglong2* yr = (const ulonglong2*)(yq + j * NPB + ib);
        ulonglong2 p0 = yr[0], p1 = yr[1], p2 = yr[2], p3 = yr[3];
        ffma2(acc0[0], p0.x, w20); ffma2(acc0[1], p0.y, w20);
        ffma2(acc0[2], p1.x, w20); ffma2(acc0[3], p1.y, w20);
        ffma2(acc0[4], p2.x, w20); ffma2(acc0[5], p2.y, w20);
        ffma2(acc0[6], p3.x, w20); ffma2(acc0[7], p3.y, w20);
        ffma2(acc1[0], p0.x, w21); ffma2(acc1[1], p0.y, w21);
        ffma2(acc1[2], p1.x, w21); ffma2(acc1[3], p1.y, w21);
        ffma2(acc1[4], p2.x, w21); ffma2(acc1[5], p2.y, w21);
        ffma2(acc1[6], p3.x, w21); ffma2(acc1[7], p3.y, w21);
    }
    #pragma unroll 4
    for (int j = 0; j < DE; j++) {
        unsigned long long w20 = pk2(Wev[j * DD + c]);
        unsigned long long w21 = pk2(Wev[j * DD + c + 64]);
        const ulonglong2* yr = (const ulonglong2*)(yq + (DD + j) * NPB + ib);
        ulonglong2 p0 = yr[0], p1 = yr[1], p2 = yr[2], p3 = yr[3];
        ffma2(acc0[0], p0.x, w20); ffma2(acc0[1], p0.y, w20);
        ffma2(acc0[2], p1.x, w20); ffma2(acc0[3], p1.y, w20);
        ffma2(acc0[4], p2.x, w20); ffma2(acc0[5], p2.y, w20);
        ffma2(acc0[6], p3.x, w20); ffma2(acc0[7], p3.y, w20);
        ffma2(acc1[0], p0.x, w21); ffma2(acc1[1], p0.y, w21);
        ffma2(acc1[2], p1.x, w21); ffma2(acc1[3], p1.y, w21);
        ffma2(acc1[4], p2.x, w21); ffma2(acc1[5], p2.y, w21);
        ffma2(acc1[6], p3.x, w21); ffma2(acc1[7], p3.y, w21);
    }

    float bb0 = bv[c] + bev[c];
    float bb1 = bv[c + 64] + bev[c + 64];
    #pragma unroll
    for (int m = 0; m < 8; m++) {
        float lo0, hi0, lo1, hi1;
        asm("mov.b64 {%0, %1}, %2;" : "=f"(lo0), "=f"(hi0) : "l"(acc0[m]));
        asm("mov.b64 {%0, %1}, %2;" : "=f"(lo1), "=f"(hi1) : "l"(acc1[m]));
        int n = n0 + ib + 2 * m;
        float a_lo = as[ib + 2 * m + 0];
        float a_hi = as[ib + 2 * m + 1];
        out[(size_t)(n + 0) * DD + c]      = lo0 + a_lo * bb0;
        out[(size_t)(n + 1) * DD + c]      = hi0 + a_hi * bb0;
        out[(size_t)(n + 0) * DD + c + 64] = lo1 + a_lo * bb1;
        out[(size_t)(n + 1) * DD + c + 64] = hi1 + a_hi * bb1;
    }
}

// ---------------------------------------------------------------------------
extern "C" void kernel_launch(void* const* d_in, const int* in_sizes, int n_in,
                              void* d_out, int out_size) {
    const float* x     = (const float*)d_in[0];
    const int*   ei    = (const int*)d_in[1];
    const float* e_emb = (const float*)d_in[2];
    const int*   bi    = (const int*)d_in[3];

    int wb = 4;
    if (n_in >= 16 && in_sizes[4] <= 1) wb = 5;
    const float* Wq  = (const float*)d_in[wb + 0];
    const float* bq  = (const float*)d_in[wb + 1];
    const float* Wk  = (const float*)d_in[wb + 2];
    const float* bk  = (const float*)d_in[wb + 3];
    const float* Wv  = (const float*)d_in[wb + 4];
    const float* bv  = (const float*)d_in[wb + 5];
    const float* Wew = (const float*)d_in[wb + 6];
    const float* bew = (const float*)d_in[wb + 7];
    const float* Wev = (const float*)d_in[wb + 8];
    const float* bev = (const float*)d_in[wb + 9];
    const float* Wa  = (const float*)d_in[wb + 10];

    float* out = (float*)d_out;

    k_prep<<<2, 256>>>(Wq, Wk, Wew, bq, bk, bew, Wa);
    k_node<<<BN / 8, 256>>>(x);
    k_edge1<<<(EE * 4) / 128, 128>>>(ei, bi, e_emb);
    k_fused<<<BN / NPB, 128>>>(x, e_emb, Wv, bv, Wev, bev, out);
    (void)out_size;
}

// round 15
// speedup vs baseline: 1.7254x; 1.0954x over previous
#include <cuda_runtime.h>
#include <cuda_bf16.h>
#include <math.h>

#define BB 4
#define NN 50000
#define BN 200000          // BB*NN
#define EE 600000
#define DD 128
#define DE 64
#define NPB 32             // nodes per fused block
#define CAP 32             // fixed bucket capacity (Poisson(3) max deg << 32)
#define NMS 196            // node-major smem stride (floats)
#define BUF_F (NPB * NMS)  // 6272 floats >= 192*NPB (6144) — shared buffer

// ---- scratch: static __device__ arrays only ----
__device__ float  g_attsum[BN];            // Σ exp(logit)      per dst
__device__ float  g_qa[BN];
__device__ float  g_ka[BN];
__device__ float4 g_wqa4[32];
__device__ float4 g_wka4[32];
__device__ float4 g_wea4[16];
__device__ float  g_cb[1];
__device__ unsigned g_cnt[BN];             // per-src bucket fill count
__device__ int4     g_meta[(size_t)BN * CAP];  // {gd, eid, ex_bits, 0}

__device__ __forceinline__ void redg(float* p, float v) {
    unsigned long long gp = (unsigned long long)__cvta_generic_to_global(p);
    asm volatile("red.global.add.f32 [%0], %1;" :: "l"(gp), "f"(v) : "memory");
}
__device__ __forceinline__ unsigned long long pk2(float x) {
    unsigned long long r;
    asm("mov.b64 %0, {%1, %1};" : "=l"(r) : "f"(x));
    return r;
}
__device__ __forceinline__ void ffma2(unsigned long long& d, unsigned long long a,
                                      unsigned long long b) {
    asm("fma.rn.f32x2 %0, %1, %2, %0;" : "+l"(d) : "l"(a), "l"(b));
}

// ---------------------------------------------------------------------------
// K0: fold Wa. Thread-per-output, contiguous float4 row reads, 2x256 threads.
// ---------------------------------------------------------------------------
__global__ __launch_bounds__(256) void k_prep(const float* __restrict__ Wq,
                                              const float* __restrict__ Wk,
                                              const float* __restrict__ Wew,
                                              const float* __restrict__ bq,
                                              const float* __restrict__ bk,
                                              const float* __restrict__ bew,
                                              const float* __restrict__ Wa) {
    int j = blockIdx.x * blockDim.x + threadIdx.x;
    const float4* wa4 = (const float4*)Wa;
    if (j < 128) {
        const float4* row = (const float4*)(Wq + (size_t)j * DD);
        float s = 0.f;
        #pragma unroll
        for (int k = 0; k < 32; k++) {
            float4 r = row[k], w = wa4[k];
            s += r.x * w.x + r.y * w.y + r.z * w.z + r.w * w.w;
        }
        ((float*)g_wqa4)[j] = s;
    } else if (j < 256) {
        const float4* row = (const float4*)(Wk + (size_t)(j - 128) * DD);
        float s = 0.f;
        #pragma unroll
        for (int k = 0; k < 32; k++) {
            float4 r = row[k], w = wa4[k];
            s += r.x * w.x + r.y * w.y + r.z * w.z + r.w * w.w;
        }
        ((float*)g_wka4)[j - 128] = s;
    } else if (j < 320) {
        const float4* row = (const float4*)(Wew + (size_t)(j - 256) * DD);
        float s = 0.f;
        #pragma unroll
        for (int k = 0; k < 32; k++) {
            float4 r = row[k], w = wa4[k];
            s += r.x * w.x + r.y * w.y + r.z * w.z + r.w * w.w;
        }
        ((float*)g_wea4)[j - 256] = s;
    } else if (j == 320) {
        float c = 0.f;
        for (int k = 0; k < DD; k++) c += (bq[k] + bk[k] + bew[k]) * Wa[k];
        g_cb[0] = c;
    }
}

// ---------------------------------------------------------------------------
// K1: per-node scalars + fused zeroing (attsum/cnt)
// ---------------------------------------------------------------------------
__global__ __launch_bounds__(256) void k_node(const float* __restrict__ x) {
    int lin = blockIdx.x * blockDim.x + threadIdx.x;
    if (lin < BN) { g_attsum[lin] = 0.f; g_cnt[lin] = 0u; }
    int w = lin >> 5;
    int lane = threadIdx.x & 31;
    if (w >= BN) return;
    float4 xv = ((const float4*)x)[(size_t)w * 32 + lane];
    float4 wq = g_wqa4[lane];
    float4 wk = g_wka4[lane];
    float pq = xv.x * wq.x + xv.y * wq.y + xv.z * wq.z + xv.w * wq.w;
    float pk = xv.x * wk.x + xv.y * wk.y + xv.z * wk.z + xv.w * wk.w;
    #pragma unroll
    for (int o = 16; o > 0; o >>= 1) {
        pq += __shfl_xor_sync(0xffffffffu, pq, o);
        pk += __shfl_xor_sync(0xffffffffu, pk, o);
    }
    if (lane == 0) { g_qa[w] = pq; g_ka[w] = pk; }
}

// ---------------------------------------------------------------------------
// edge pass: logit/exp, attsum reduction, direct bucket scatter
// ---------------------------------------------------------------------------
__global__ __launch_bounds__(128) void k_edge1(const int* __restrict__ ei,
                                               const int* __restrict__ bi,
                                               const float* __restrict__ e_emb) {
    int t = blockIdx.x * blockDim.x + threadIdx.x;
    int e = t >> 2;
    int sub = t & 3;
    if (e >= EE) return;
    const float4* er = (const float4*)(e_emb + (size_t)e * DE);
    float p = 0.f;
    #pragma unroll
    for (int i = 0; i < 4; i++) {
        float4 v  = er[sub * 4 + i];
        float4 wv = g_wea4[sub * 4 + i];
        p += v.x * wv.x + v.y * wv.y + v.z * wv.z + v.w * wv.w;
    }
    p += __shfl_xor_sync(0xffffffffu, p, 1);
    p += __shfl_xor_sync(0xffffffffu, p, 2);
    if (sub == 0) {
        int s = ei[e];
        int d = ei[EE + e];
        int b = bi[e];
        int gs = b * NN + s;
        int gd = b * NN + d;
        float logit = (g_qa[gs] + g_ka[gd] + p + g_cb[0]) * 0.25f;
        float ex = expf(logit);
        redg(&g_attsum[gd], ex);
        unsigned idx = atomicAdd(&g_cnt[gs], 1u);
        g_meta[(size_t)gs * CAP + idx] = make_int4(gd, e, __float_as_int(ex), 0);
    }
}

// ---------------------------------------------------------------------------
// FUSED gather + epilogue v3: 128 threads / 32 nodes, 5 CTAs/SM.
//   Phase 1: gather -> node-major into shared buf (un-unrolled node loop).
//   Phase 2: register-staged in-place transpose (reads ALL before writes).
//   Phase 3: FFMA2 epilogue, 2 columns per thread (verbatim R14).
// Single 25.1 KB smem buffer -> occupancy limited by regs only (cap 102).
// ---------------------------------------------------------------------------
__global__ __launch_bounds__(128, 5) void k_fused(const float* __restrict__ x,
                                                  const float* __restrict__ e_emb,
                                                  const float* __restrict__ Wv,
                                                  const float* __restrict__ bv,
                                                  const float* __restrict__ Wev,
                                                  const float* __restrict__ bev,
                                                  float* __restrict__ out) {
    __shared__ __align__(16) float buf[BUF_F];  // ynm then (after transpose) yq
    __shared__ float as[NPB];
    int t = threadIdx.x;
    int n0 = blockIdx.x * NPB;
    int w = t >> 5, lane = t & 31;

    // ---- Phase 1: gather (proven batch-4 loop), 8 nodes per warp ----
    {
        const int4 mz = make_int4(0, 0, 0, 0);
        #pragma unroll 1
        for (int nn = 0; nn < 8; nn++) {
            int li = w * 8 + nn;
            int gs = n0 + li;
            unsigned deg = g_cnt[gs];
            const int4* mrow = g_meta + (size_t)gs * CAP;

            float4 ya = make_float4(0.f, 0.f, 0.f, 0.f);
            float4 ua = make_float4(0.f, 0.f, 0.f, 0.f);
            float asum = 0.f;

            for (unsigned p = 0; p < deg; p += 4) {
                int4 m0 = mrow[p];
                int4 m1 = (p + 1 < deg) ? mrow[p + 1] : mz;
                int4 m2 = (p + 2 < deg) ? mrow[p + 2] : mz;
                int4 m3 = (p + 3 < deg) ? mrow[p + 3] : mz;

                float s0 = g_attsum[m0.x];
                float s1 = g_attsum[m1.x];
                float s2 = g_attsum[m2.x];
                float s3 = g_attsum[m3.x];
                float a0 = __fdividef(__int_as_float(m0.z), s0 + 1e-9f);
                float a1 = __fdividef(__int_as_float(m1.z), s1 + 1e-9f);
                float a2 = __fdividef(__int_as_float(m2.z), s2 + 1e-9f);
                float a3 = __fdividef(__int_as_float(m3.z), s3 + 1e-9f);

                float4 x0 = ((const float4*)x)[(size_t)m0.x * 32 + lane];
                float4 x1 = ((const float4*)x)[(size_t)m1.x * 32 + lane];
                float4 x2 = ((const float4*)x)[(size_t)m2.x * 32 + lane];
                float4 x3 = ((const float4*)x)[(size_t)m3.x * 32 + lane];

                if (lane < 16) {
                    float4 e0 = __ldcs((const float4*)e_emb + (size_t)m0.y * 16 + lane);
                    float4 e1 = __ldcs((const float4*)e_emb + (size_t)m1.y * 16 + lane);
                    float4 e2 = __ldcs((const float4*)e_emb + (size_t)m2.y * 16 + lane);
                    float4 e3 = __ldcs((const float4*)e_emb + (size_t)m3.y * 16 + lane);
                    ua.x += a0 * e0.x + a1 * e1.x + a2 * e2.x + a3 * e3.x;
                    ua.y += a0 * e0.y + a1 * e1.y + a2 * e2.y + a3 * e3.y;
                    ua.z += a0 * e0.z + a1 * e1.z + a2 * e2.z + a3 * e3.z;
                    ua.w += a0 * e0.w + a1 * e1.w + a2 * e2.w + a3 * e3.w;
                }

                ya.x += a0 * x0.x + a1 * x1.x + a2 * x2.x + a3 * x3.x;
                ya.y += a0 * x0.y + a1 * x1.y + a2 * x2.y + a3 * x3.y;
                ya.z += a0 * x0.z + a1 * x1.z + a2 * x2.z + a3 * x3.z;
                ya.w += a0 * x0.w + a1 * x1.w + a2 * x2.w + a3 * x3.w;
                asum += a0 + a1 + a2 + a3;
            }
            *(float4*)(buf + li * NMS + 4 * lane) = ya;
            if (lane < 16)
                *(float4*)(buf + li * NMS + DD + 4 * lane) = ua;
            if (lane == 0) as[li] = asum;
        }
    }
    __syncthreads();

    // ---- Phase 2: register-staged in-place transpose -> yq[j][32] ----
    {
        int i = t & 31, g = t >> 5;     // node i, chunk g in 0..3
        float4 ry[8], ru[4];
        #pragma unroll
        for (int q = 0; q < 8; q++)
            ry[q] = *(const float4*)(buf + i * NMS + g * 32 + q * 4);
        #pragma unroll
        for (int q = 0; q < 4; q++)
            ru[q] = *(const float4*)(buf + i * NMS + DD + g * 16 + q * 4);
        __syncthreads();               // ALL reads done before ANY write
        #pragma unroll
        for (int q = 0; q < 8; q++) {
            int j = g * 32 + q * 4;
            buf[(j + 0) * NPB + i] = ry[q].x;
            buf[(j + 1) * NPB + i] = ry[q].y;
            buf[(j + 2) * NPB + i] = ry[q].z;
            buf[(j + 3) * NPB + i] = ry[q].w;
        }
        #pragma unroll
        for (int q = 0; q < 4; q++) {
            int j = DD + g * 16 + q * 4;
            buf[(j + 0) * NPB + i] = ru[q].x;
            buf[(j + 1) * NPB + i] = ru[q].y;
            buf[(j + 2) * NPB + i] = ru[q].z;
            buf[(j + 3) * NPB + i] = ru[q].w;
        }
    }
    __syncthreads();

    // ---- Phase 3: epilogue — 2 cols/thread, node-half per warp-pair ----
    const float* yq = buf;
    int c = t & 63;                 // column base (second col = c+64)
    int h = t >> 6;                 // node half: 0 or 1
    int ib = h * 16;
    unsigned long long acc0[8] = {0, 0, 0, 0, 0, 0, 0, 0};
    unsigned long long acc1[8] = {0, 0, 0, 0, 0, 0, 0, 0};

    #pragma unroll 4
    for (int j = 0; j < DD; j++) {
        unsigned long long w20 = pk2(Wv[j * DD + c]);
        unsigned long long w21 = pk2(Wv[j * DD + c + 64]);
        const ulonglong2* yr = (const ulonglong2*)(yq + j * NPB + ib);
        ulonglong2 p0 = yr[0], p1 = yr[1], p2 = yr[2], p3 = yr[3];
        ffma2(acc0[0], p0.x, w20); ffma2(acc0[1], p0.y, w20);
        ffma2(acc0[2], p1.x, w20); ffma2(acc0[3], p1.y, w20);
        ffma2(acc0[4], p2.x, w20); ffma2(acc0[5], p2.y, w20);
        ffma2(acc0[6], p3.x, w20); ffma2(acc0[7], p3.y, w20);
        ffma2(acc1[0], p0.x, w21); ffma2(acc1[1], p0.y, w21);
        ffma2(acc1[2], p1.x, w21); ffma2(acc1[3], p1.y, w21);
        ffma2(acc1[4], p2.x, w21); ffma2(acc1[5], p2.y, w21);
        ffma2(acc1[6], p3.x, w21); ffma2(acc1[7], p3.y, w21);
    }
    #pragma unroll 4
    for (int j = 0; j < DE; j++) {
        unsigned long long w20 = pk2(Wev[j * DD + c]);
        unsigned long long w21 = pk2(Wev[j * DD + c + 64]);
        const ulonglong2* yr = (const ulonglong2*)(yq + (DD + j) * NPB + ib);
        ulonglong2 p0 = yr[0], p1 = yr[1], p2 = yr[2], p3 = yr[3];
        ffma2(acc0[0], p0.x, w20); ffma2(acc0[1], p0.y, w20);
        ffma2(acc0[2], p1.x, w20); ffma2(acc0[3], p1.y, w20);
        ffma2(acc0[4], p2.x, w20); ffma2(acc0[5], p2.y, w20);
        ffma2(acc0[6], p3.x, w20); ffma2(acc0[7], p3.y, w20);
        ffma2(acc1[0], p0.x, w21); ffma2(acc1[1], p0.y, w21);
        ffma2(acc1[2], p1.x, w21); ffma2(acc1[3], p1.y, w21);
        ffma2(acc1[4], p2.x, w21); ffma2(acc1[5], p2.y, w21);
        ffma2(acc1[6], p3.x, w21); ffma2(acc1[7], p3.y, w21);
    }

    float bb0 = bv[c] + bev[c];
    float bb1 = bv[c + 64] + bev[c + 64];
    #pragma unroll
    for (int m = 0; m < 8; m++) {
        float lo0, hi0, lo1, hi1;
        asm("mov.b64 {%0, %1}, %2;" : "=f"(lo0), "=f"(hi0) : "l"(acc0[m]));
        asm("mov.b64 {%0, %1}, %2;" : "=f"(lo1), "=f"(hi1) : "l"(acc1[m]));
        int n = n0 + ib + 2 * m;
        float a_lo = as[ib + 2 * m + 0];
        float a_hi = as[ib + 2 * m + 1];
        out[(size_t)(n + 0) * DD + c]      = lo0 + a_lo * bb0;
        out[(size_t)(n + 1) * DD + c]      = hi0 + a_hi * bb0;
        out[(size_t)(n + 0) * DD + c + 64] = lo1 + a_lo * bb1;
        out[(size_t)(n + 1) * DD + c + 64] = hi1 + a_hi * bb1;
    }
}

// ---------------------------------------------------------------------------
extern "C" void kernel_launch(void* const* d_in, const int* in_sizes, int n_in,
                              void* d_out, int out_size) {
    const float* x     = (const float*)d_in[0];
    const int*   ei    = (const int*)d_in[1];
    const float* e_emb = (const float*)d_in[2];
    const int*   bi    = (const int*)d_in[3];

    int wb = 4;
    if (n_in >= 16 && in_sizes[4] <= 1) wb = 5;
    const float* Wq  = (const float*)d_in[wb + 0];
    const float* bq  = (const float*)d_in[wb + 1];
    const float* Wk  = (const float*)d_in[wb + 2];
    const float* bk  = (const float*)d_in[wb + 3];
    const float* Wv  = (const float*)d_in[wb + 4];
    const float* bv  = (const float*)d_in[wb + 5];
    const float* Wew = (const float*)d_in[wb + 6];
    const float* bew = (const float*)d_in[wb + 7];
    const float* Wev = (const float*)d_in[wb + 8];
    const float* bev = (const float*)d_in[wb + 9];
    const float* Wa  = (const float*)d_in[wb + 10];

    float* out = (float*)d_out;

    k_prep<<<2, 256>>>(Wq, Wk, Wew, bq, bk, bew, Wa);
    k_node<<<BN / 8, 256>>>(x);
    k_edge1<<<(EE * 4) / 128, 128>>>(ei, bi, e_emb);
    k_fused<<<BN / NPB, 128>>>(x, e_emb, Wv, bv, Wev, bev, out);
    (void)out_size;
}

// round 16
// speedup vs baseline: 1.7811x; 1.0323x over previous
#include <cuda_runtime.h>
#include <cuda_bf16.h>
#include <math.h>

#define BB 4
#define NN 50000
#define BN 200000          // BB*NN
#define EE 600000
#define DD 128
#define DE 64
#define NPB 32             // nodes per fused block
#define CAP 32             // fixed bucket capacity
#define NMS 196            // node-major smem stride (floats)
#define BUF_F (NPB * NMS)  // shared buffer floats

// ---- scratch: static __device__ arrays only ----
__device__ float  g_attsum[BN];
__device__ float  g_qa[BN];
__device__ float  g_ka[BN];
__device__ float4 g_wqa4[32];
__device__ float4 g_wka4[32];
__device__ float4 g_wea4[16];
__device__ float  g_cb[1];
__device__ unsigned g_cnt[BN];
__device__ int4     g_meta[(size_t)BN * CAP];  // {gd, eid, ex_bits, 0}

__device__ __forceinline__ void redg(float* p, float v) {
    unsigned long long gp = (unsigned long long)__cvta_generic_to_global(p);
    asm volatile("red.global.add.f32 [%0], %1;" :: "l"(gp), "f"(v) : "memory");
}
__device__ __forceinline__ unsigned long long pk2(float x) {
    unsigned long long r;
    asm("mov.b64 %0, {%1, %1};" : "=l"(r) : "f"(x));
    return r;
}
__device__ __forceinline__ void ffma2(unsigned long long& d, unsigned long long a,
                                      unsigned long long b) {
    asm("fma.rn.f32x2 %0, %1, %2, %0;" : "+l"(d) : "l"(a), "l"(b));
}

// ---------------------------------------------------------------------------
__global__ __launch_bounds__(256) void k_prep(const float* __restrict__ Wq,
                                              const float* __restrict__ Wk,
                                              const float* __restrict__ Wew,
                                              const float* __restrict__ bq,
                                              const float* __restrict__ bk,
                                              const float* __restrict__ bew,
                                              const float* __restrict__ Wa) {
    int j = blockIdx.x * blockDim.x + threadIdx.x;
    const float4* wa4 = (const float4*)Wa;
    if (j < 128) {
        const float4* row = (const float4*)(Wq + (size_t)j * DD);
        float s = 0.f;
        #pragma unroll
        for (int k = 0; k < 32; k++) {
            float4 r = row[k], w = wa4[k];
            s += r.x * w.x + r.y * w.y + r.z * w.z + r.w * w.w;
        }
        ((float*)g_wqa4)[j] = s;
    } else if (j < 256) {
        const float4* row = (const float4*)(Wk + (size_t)(j - 128) * DD);
        float s = 0.f;
        #pragma unroll
        for (int k = 0; k < 32; k++) {
            float4 r = row[k], w = wa4[k];
            s += r.x * w.x + r.y * w.y + r.z * w.z + r.w * w.w;
        }
        ((float*)g_wka4)[j - 128] = s;
    } else if (j < 320) {
        const float4* row = (const float4*)(Wew + (size_t)(j - 256) * DD);
        float s = 0.f;
        #pragma unroll
        for (int k = 0; k < 32; k++) {
            float4 r = row[k], w = wa4[k];
            s += r.x * w.x + r.y * w.y + r.z * w.z + r.w * w.w;
        }
        ((float*)g_wea4)[j - 256] = s;
    } else if (j == 320) {
        float c = 0.f;
        for (int k = 0; k < DD; k++) c += (bq[k] + bk[k] + bew[k]) * Wa[k];
        g_cb[0] = c;
    }
}

// ---------------------------------------------------------------------------
__global__ __launch_bounds__(256) void k_node(const float* __restrict__ x) {
    int lin = blockIdx.x * blockDim.x + threadIdx.x;
    if (lin < BN) { g_attsum[lin] = 0.f; g_cnt[lin] = 0u; }
    int w = lin >> 5;
    int lane = threadIdx.x & 31;
    if (w >= BN) return;
    float4 xv = ((const float4*)x)[(size_t)w * 32 + lane];
    float4 wq = g_wqa4[lane];
    float4 wk = g_wka4[lane];
    float pq = xv.x * wq.x + xv.y * wq.y + xv.z * wq.z + xv.w * wq.w;
    float pk = xv.x * wk.x + xv.y * wk.y + xv.z * wk.z + xv.w * wk.w;
    #pragma unroll
    for (int o = 16; o > 0; o >>= 1) {
        pq += __shfl_xor_sync(0xffffffffu, pq, o);
        pk += __shfl_xor_sync(0xffffffffu, pk, o);
    }
    if (lane == 0) { g_qa[w] = pq; g_ka[w] = pk; }
}

// ---------------------------------------------------------------------------
__global__ __launch_bounds__(128) void k_edge1(const int* __restrict__ ei,
                                               const int* __restrict__ bi,
                                               const float* __restrict__ e_emb) {
    int t = blockIdx.x * blockDim.x + threadIdx.x;
    int e = t >> 2;
    int sub = t & 3;
    if (e >= EE) return;
    const float4* er = (const float4*)(e_emb + (size_t)e * DE);
    float p = 0.f;
    #pragma unroll
    for (int i = 0; i < 4; i++) {
        float4 v  = er[sub * 4 + i];
        float4 wv = g_wea4[sub * 4 + i];
        p += v.x * wv.x + v.y * wv.y + v.z * wv.z + v.w * wv.w;
    }
    p += __shfl_xor_sync(0xffffffffu, p, 1);
    p += __shfl_xor_sync(0xffffffffu, p, 2);
    if (sub == 0) {
        int s = ei[e];
        int d = ei[EE + e];
        int b = bi[e];
        int gs = b * NN + s;
        int gd = b * NN + d;
        float logit = (g_qa[gs] + g_ka[gd] + p + g_cb[0]) * 0.25f;
        float ex = expf(logit);
        redg(&g_attsum[gd], ex);
        unsigned idx = atomicAdd(&g_cnt[gs], 1u);
        g_meta[(size_t)gs * CAP + idx] = make_int4(gd, e, __float_as_int(ex), 0);
    }
}

// ---------------------------------------------------------------------------
// FUSED gather + epilogue v4: as R15, but dummy batch-slots issue NO loads
// (warp-uniform predication; alpha explicitly 0 for inactive slots).
// ---------------------------------------------------------------------------
__global__ __launch_bounds__(128, 5) void k_fused(const float* __restrict__ x,
                                                  const float* __restrict__ e_emb,
                                                  const float* __restrict__ Wv,
                                                  const float* __restrict__ bv,
                                                  const float* __restrict__ Wev,
                                                  const float* __restrict__ bev,
                                                  float* __restrict__ out) {
    __shared__ __align__(16) float buf[BUF_F];
    __shared__ float as[NPB];
    int t = threadIdx.x;
    int n0 = blockIdx.x * NPB;
    int w = t >> 5, lane = t & 31;

    // ---- Phase 1: gather, 8 nodes per warp, no dummy loads ----
    {
        #pragma unroll 1
        for (int nn = 0; nn < 8; nn++) {
            int li = w * 8 + nn;
            int gs = n0 + li;
            unsigned deg = g_cnt[gs];
            const int4* mrow = g_meta + (size_t)gs * CAP;

            float4 ya = make_float4(0.f, 0.f, 0.f, 0.f);
            float4 ua = make_float4(0.f, 0.f, 0.f, 0.f);
            float asum = 0.f;

            for (unsigned p = 0; p < deg; p += 4) {
                bool v1 = (p + 1 < deg), v2 = (p + 2 < deg), v3 = (p + 3 < deg);
                int4 m0 = mrow[p];
                int4 m1, m2, m3;
                m1.x = m1.y = m1.z = 0;
                m2.x = m2.y = m2.z = 0;
                m3.x = m3.y = m3.z = 0;
                if (v1) m1 = mrow[p + 1];
                if (v2) m2 = mrow[p + 2];
                if (v3) m3 = mrow[p + 3];

                float s0 = g_attsum[m0.x];
                float s1 = 1.f, s2 = 1.f, s3 = 1.f;
                if (v1) s1 = g_attsum[m1.x];
                if (v2) s2 = g_attsum[m2.x];
                if (v3) s3 = g_attsum[m3.x];
                float a0 = __fdividef(__int_as_float(m0.z), s0 + 1e-9f);
                float a1 = v1 ? __fdividef(__int_as_float(m1.z), s1 + 1e-9f) : 0.f;
                float a2 = v2 ? __fdividef(__int_as_float(m2.z), s2 + 1e-9f) : 0.f;
                float a3 = v3 ? __fdividef(__int_as_float(m3.z), s3 + 1e-9f) : 0.f;

                float4 x0 = ((const float4*)x)[(size_t)m0.x * 32 + lane];
                float4 x1 = make_float4(0.f, 0.f, 0.f, 0.f);
                float4 x2 = make_float4(0.f, 0.f, 0.f, 0.f);
                float4 x3 = make_float4(0.f, 0.f, 0.f, 0.f);
                if (v1) x1 = ((const float4*)x)[(size_t)m1.x * 32 + lane];
                if (v2) x2 = ((const float4*)x)[(size_t)m2.x * 32 + lane];
                if (v3) x3 = ((const float4*)x)[(size_t)m3.x * 32 + lane];

                if (lane < 16) {
                    float4 e0 = __ldcs((const float4*)e_emb + (size_t)m0.y * 16 + lane);
                    float4 e1 = make_float4(0.f, 0.f, 0.f, 0.f);
                    float4 e2 = make_float4(0.f, 0.f, 0.f, 0.f);
                    float4 e3 = make_float4(0.f, 0.f, 0.f, 0.f);
                    if (v1) e1 = __ldcs((const float4*)e_emb + (size_t)m1.y * 16 + lane);
                    if (v2) e2 = __ldcs((const float4*)e_emb + (size_t)m2.y * 16 + lane);
                    if (v3) e3 = __ldcs((const float4*)e_emb + (size_t)m3.y * 16 + lane);
                    ua.x += a0 * e0.x + a1 * e1.x + a2 * e2.x + a3 * e3.x;
                    ua.y += a0 * e0.y + a1 * e1.y + a2 * e2.y + a3 * e3.y;
                    ua.z += a0 * e0.z + a1 * e1.z + a2 * e2.z + a3 * e3.z;
                    ua.w += a0 * e0.w + a1 * e1.w + a2 * e2.w + a3 * e3.w;
                }

                ya.x += a0 * x0.x + a1 * x1.x + a2 * x2.x + a3 * x3.x;
                ya.y += a0 * x0.y + a1 * x1.y + a2 * x2.y + a3 * x3.y;
                ya.z += a0 * x0.z + a1 * x1.z + a2 * x2.z + a3 * x3.z;
                ya.w += a0 * x0.w + a1 * x1.w + a2 * x2.w + a3 * x3.w;
                asum += a0 + a1 + a2 + a3;
            }
            *(float4*)(buf + li * NMS + 4 * lane) = ya;
            if (lane < 16)
                *(float4*)(buf + li * NMS + DD + 4 * lane) = ua;
            if (lane == 0) as[li] = asum;
        }
    }
    __syncthreads();

    // ---- Phase 2: register-staged in-place transpose -> yq[j][32] ----
    {
        int i = t & 31, g = t >> 5;
        float4 ry[8], ru[4];
        #pragma unroll
        for (int q = 0; q < 8; q++)
            ry[q] = *(const float4*)(buf + i * NMS + g * 32 + q * 4);
        #pragma unroll
        for (int q = 0; q < 4; q++)
            ru[q] = *(const float4*)(buf + i * NMS + DD + g * 16 + q * 4);
        __syncthreads();
        #pragma unroll
        for (int q = 0; q < 8; q++) {
            int j = g * 32 + q * 4;
            buf[(j + 0) * NPB + i] = ry[q].x;
            buf[(j + 1) * NPB + i] = ry[q].y;
            buf[(j + 2) * NPB + i] = ry[q].z;
            buf[(j + 3) * NPB + i] = ry[q].w;
        }
        #pragma unroll
        for (int q = 0; q < 4; q++) {
            int j = DD + g * 16 + q * 4;
            buf[(j + 0) * NPB + i] = ru[q].x;
            buf[(j + 1) * NPB + i] = ru[q].y;
            buf[(j + 2) * NPB + i] = ru[q].z;
            buf[(j + 3) * NPB + i] = ru[q].w;
        }
    }
    __syncthreads();

    // ---- Phase 3: epilogue — 2 cols/thread, node-half per warp-pair ----
    const float* yq = buf;
    int c = t & 63;
    int h = t >> 6;
    int ib = h * 16;
    unsigned long long acc0[8] = {0, 0, 0, 0, 0, 0, 0, 0};
    unsigned long long acc1[8] = {0, 0, 0, 0, 0, 0, 0, 0};

    #pragma unroll 4
    for (int j = 0; j < DD; j++) {
        unsigned long long w20 = pk2(Wv[j * DD + c]);
        unsigned long long w21 = pk2(Wv[j * DD + c + 64]);
        const ulonglong2* yr = (const ulonglong2*)(yq + j * NPB + ib);
        ulonglong2 p0 = yr[0], p1 = yr[1], p2 = yr[2], p3 = yr[3];
        ffma2(acc0[0], p0.x, w20); ffma2(acc0[1], p0.y, w20);
        ffma2(acc0[2], p1.x, w20); ffma2(acc0[3], p1.y, w20);
        ffma2(acc0[4], p2.x, w20); ffma2(acc0[5], p2.y, w20);
        ffma2(acc0[6], p3.x, w20); ffma2(acc0[7], p3.y, w20);
        ffma2(acc1[0], p0.x, w21); ffma2(acc1[1], p0.y, w21);
        ffma2(acc1[2], p1.x, w21); ffma2(acc1[3], p1.y, w21);
        ffma2(acc1[4], p2.x, w21); ffma2(acc1[5], p2.y, w21);
        ffma2(acc1[6], p3.x, w21); ffma2(acc1[7], p3.y, w21);
    }
    #pragma unroll 4
    for (int j = 0; j < DE; j++) {
        unsigned long long w20 = pk2(Wev[j * DD + c]);
        unsigned long long w21 = pk2(Wev[j * DD + c + 64]);
        const ulonglong2* yr = (const ulonglong2*)(yq + (DD + j) * NPB + ib);
        ulonglong2 p0 = yr[0], p1 = yr[1], p2 = yr[2], p3 = yr[3];
        ffma2(acc0[0], p0.x, w20); ffma2(acc0[1], p0.y, w20);
        ffma2(acc0[2], p1.x, w20); ffma2(acc0[3], p1.y, w20);
        ffma2(acc0[4], p2.x, w20); ffma2(acc0[5], p2.y, w20);
        ffma2(acc0[6], p3.x, w20); ffma2(acc0[7], p3.y, w20);
        ffma2(acc1[0], p0.x, w21); ffma2(acc1[1], p0.y, w21);
        ffma2(acc1[2], p1.x, w21); ffma2(acc1[3], p1.y, w21);
        ffma2(acc1[4], p2.x, w21); ffma2(acc1[5], p2.y, w21);
        ffma2(acc1[6], p3.x, w21); ffma2(acc1[7], p3.y, w21);
    }

    float bb0 = bv[c] + bev[c];
    float bb1 = bv[c + 64] + bev[c + 64];
    #pragma unroll
    for (int m = 0; m < 8; m++) {
        float lo0, hi0, lo1, hi1;
        asm("mov.b64 {%0, %1}, %2;" : "=f"(lo0), "=f"(hi0) : "l"(acc0[m]));
        asm("mov.b64 {%0, %1}, %2;" : "=f"(lo1), "=f"(hi1) : "l"(acc1[m]));
        int n = n0 + ib + 2 * m;
        float a_lo = as[ib + 2 * m + 0];
        float a_hi = as[ib + 2 * m + 1];
        out[(size_t)(n + 0) * DD + c]      = lo0 + a_lo * bb0;
        out[(size_t)(n + 1) * DD + c]      = hi0 + a_hi * bb0;
        out[(size_t)(n + 0) * DD + c + 64] = lo1 + a_lo * bb1;
        out[(size_t)(n + 1) * DD + c + 64] = hi1 + a_hi * bb1;
    }
}

// ---------------------------------------------------------------------------
extern "C" void kernel_launch(void* const* d_in, const int* in_sizes, int n_in,
                              void* d_out, int out_size) {
    const float* x     = (const float*)d_in[0];
    const int*   ei    = (const int*)d_in[1];
    const float* e_emb = (const float*)d_in[2];
    const int*   bi    = (const int*)d_in[3];

    int wb = 4;
    if (n_in >= 16 && in_sizes[4] <= 1) wb = 5;
    const float* Wq  = (const float*)d_in[wb + 0];
    const float* bq  = (const float*)d_in[wb + 1];
    const float* Wk  = (const float*)d_in[wb + 2];
    const float* bk  = (const float*)d_in[wb + 3];
    const float* Wv  = (const float*)d_in[wb + 4];
    const float* bv  = (const float*)d_in[wb + 5];
    const float* Wew = (const float*)d_in[wb + 6];
    const float* bew = (const float*)d_in[wb + 7];
    const float* Wev = (const float*)d_in[wb + 8];
    const float* bev = (const float*)d_in[wb + 9];
    const float* Wa  = (const float*)d_in[wb + 10];

    float* out = (float*)d_out;

    k_prep<<<2, 256>>>(Wq, Wk, Wew, bq, bk, bew, Wa);
    k_node<<<BN / 8, 256>>>(x);
    k_edge1<<<(EE * 4) / 128, 128>>>(ei, bi, e_emb);
    k_fused<<<BN / NPB, 128>>>(x, e_emb, Wv, bv, Wev, bev, out);
    (void)out_size;
}

// round 17
// speedup vs baseline: 1.8859x; 1.0589x over previous
#include <cuda_runtime.h>
#include <cuda_bf16.h>
#include <math.h>

#define BB 4
#define NN 50000
#define BN 200000          // BB*NN
#define EE 600000
#define DD 128
#define DE 64
#define NPB 32             // nodes per fused block
#define CAP 32             // fixed bucket capacity
#define NMS 196            // node-major smem stride (floats)
#define BUF_F (NPB * NMS)  // shared buffer floats

// ---- scratch: static __device__ arrays only ----
__device__ float  g_attsum[BN];
__device__ float  g_qa[BN];
__device__ float  g_ka[BN];
__device__ float4 g_wqa4[32];
__device__ float4 g_wka4[32];
__device__ float4 g_wea4[16];
__device__ float  g_cb[1];
__device__ unsigned g_cnt[BN];
__device__ int4     g_meta[(size_t)BN * CAP];  // {gd, eid, ex_bits, 0}

__device__ __forceinline__ void redg(float* p, float v) {
    unsigned long long gp = (unsigned long long)__cvta_generic_to_global(p);
    asm volatile("red.global.add.f32 [%0], %1;" :: "l"(gp), "f"(v) : "memory");
}
__device__ __forceinline__ unsigned long long pk2(float x) {
    unsigned long long r;
    asm("mov.b64 %0, {%1, %1};" : "=l"(r) : "f"(x));
    return r;
}
__device__ __forceinline__ void ffma2(unsigned long long& d, unsigned long long a,
                                      unsigned long long b) {
    asm("fma.rn.f32x2 %0, %1, %2, %0;" : "+l"(d) : "l"(a), "l"(b));
}

// ---------------------------------------------------------------------------
__global__ __launch_bounds__(256) void k_prep(const float* __restrict__ Wq,
                                              const float* __restrict__ Wk,
                                              const float* __restrict__ Wew,
                                              const float* __restrict__ bq,
                                              const float* __restrict__ bk,
                                              const float* __restrict__ bew,
                                              const float* __restrict__ Wa) {
    int j = blockIdx.x * blockDim.x + threadIdx.x;
    const float4* wa4 = (const float4*)Wa;
    if (j < 128) {
        const float4* row = (const float4*)(Wq + (size_t)j * DD);
        float s = 0.f;
        #pragma unroll
        for (int k = 0; k < 32; k++) {
            float4 r = row[k], w = wa4[k];
            s += r.x * w.x + r.y * w.y + r.z * w.z + r.w * w.w;
        }
        ((float*)g_wqa4)[j] = s;
    } else if (j < 256) {
        const float4* row = (const float4*)(Wk + (size_t)(j - 128) * DD);
        float s = 0.f;
        #pragma unroll
        for (int k = 0; k < 32; k++) {
            float4 r = row[k], w = wa4[k];
            s += r.x * w.x + r.y * w.y + r.z * w.z + r.w * w.w;
        }
        ((float*)g_wka4)[j - 128] = s;
    } else if (j < 320) {
        const float4* row = (const float4*)(Wew + (size_t)(j - 256) * DD);
        float s = 0.f;
        #pragma unroll
        for (int k = 0; k < 32; k++) {
            float4 r = row[k], w = wa4[k];
            s += r.x * w.x + r.y * w.y + r.z * w.z + r.w * w.w;
        }
        ((float*)g_wea4)[j - 256] = s;
    } else if (j == 320) {
        float c = 0.f;
        for (int k = 0; k < DD; k++) c += (bq[k] + bk[k] + bew[k]) * Wa[k];
        g_cb[0] = c;
    }
}

// ---------------------------------------------------------------------------
__global__ __launch_bounds__(256) void k_node(const float* __restrict__ x) {
    int lin = blockIdx.x * blockDim.x + threadIdx.x;
    if (lin < BN) { g_attsum[lin] = 0.f; g_cnt[lin] = 0u; }
    int w = lin >> 5;
    int lane = threadIdx.x & 31;
    if (w >= BN) return;
    float4 xv = ((const float4*)x)[(size_t)w * 32 + lane];
    float4 wq = g_wqa4[lane];
    float4 wk = g_wka4[lane];
    float pq = xv.x * wq.x + xv.y * wq.y + xv.z * wq.z + xv.w * wq.w;
    float pk = xv.x * wk.x + xv.y * wk.y + xv.z * wk.z + xv.w * wk.w;
    #pragma unroll
    for (int o = 16; o > 0; o >>= 1) {
        pq += __shfl_xor_sync(0xffffffffu, pq, o);
        pk += __shfl_xor_sync(0xffffffffu, pk, o);
    }
    if (lane == 0) { g_qa[w] = pq; g_ka[w] = pk; }
}

// ---------------------------------------------------------------------------
__global__ __launch_bounds__(128) void k_edge1(const int* __restrict__ ei,
                                               const int* __restrict__ bi,
                                               const float* __restrict__ e_emb) {
    int t = blockIdx.x * blockDim.x + threadIdx.x;
    int e = t >> 2;
    int sub = t & 3;
    if (e >= EE) return;
    const float4* er = (const float4*)(e_emb + (size_t)e * DE);
    float p = 0.f;
    #pragma unroll
    for (int i = 0; i < 4; i++) {
        float4 v  = er[sub * 4 + i];
        float4 wv = g_wea4[sub * 4 + i];
        p += v.x * wv.x + v.y * wv.y + v.z * wv.z + v.w * wv.w;
    }
    p += __shfl_xor_sync(0xffffffffu, p, 1);
    p += __shfl_xor_sync(0xffffffffu, p, 2);
    if (sub == 0) {
        int s = ei[e];
        int d = ei[EE + e];
        int b = bi[e];
        int gs = b * NN + s;
        int gd = b * NN + d;
        float logit = (g_qa[gs] + g_ka[gd] + p + g_cb[0]) * 0.25f;
        float ex = expf(logit);
        redg(&g_attsum[gd], ex);
        unsigned idx = atomicAdd(&g_cnt[gs], 1u);
        g_meta[(size_t)gs * CAP + idx] = make_int4(gd, e, __float_as_int(ex), 0);
    }
}

// ---------------------------------------------------------------------------
// FUSED gather + epilogue v5: identical to R16 except 6 CTAs/SM forced
// (reg cap 85) — trades a few spills for +20% resident warps.
// ---------------------------------------------------------------------------
__global__ __launch_bounds__(128, 6) void k_fused(const float* __restrict__ x,
                                                  const float* __restrict__ e_emb,
                                                  const float* __restrict__ Wv,
                                                  const float* __restrict__ bv,
                                                  const float* __restrict__ Wev,
                                                  const float* __restrict__ bev,
                                                  float* __restrict__ out) {
    __shared__ __align__(16) float buf[BUF_F];
    __shared__ float as[NPB];
    int t = threadIdx.x;
    int n0 = blockIdx.x * NPB;
    int w = t >> 5, lane = t & 31;

    // ---- Phase 1: gather, 8 nodes per warp, no dummy loads ----
    {
        #pragma unroll 1
        for (int nn = 0; nn < 8; nn++) {
            int li = w * 8 + nn;
            int gs = n0 + li;
            unsigned deg = g_cnt[gs];
            const int4* mrow = g_meta + (size_t)gs * CAP;

            float4 ya = make_float4(0.f, 0.f, 0.f, 0.f);
            float4 ua = make_float4(0.f, 0.f, 0.f, 0.f);
            float asum = 0.f;

            for (unsigned p = 0; p < deg; p += 4) {
                bool v1 = (p + 1 < deg), v2 = (p + 2 < deg), v3 = (p + 3 < deg);
                int4 m0 = mrow[p];
                int4 m1, m2, m3;
                m1.x = m1.y = m1.z = 0;
                m2.x = m2.y = m2.z = 0;
                m3.x = m3.y = m3.z = 0;
                if (v1) m1 = mrow[p + 1];
                if (v2) m2 = mrow[p + 2];
                if (v3) m3 = mrow[p + 3];

                float s0 = g_attsum[m0.x];
                float s1 = 1.f, s2 = 1.f, s3 = 1.f;
                if (v1) s1 = g_attsum[m1.x];
                if (v2) s2 = g_attsum[m2.x];
                if (v3) s3 = g_attsum[m3.x];
                float a0 = __fdividef(__int_as_float(m0.z), s0 + 1e-9f);
                float a1 = v1 ? __fdividef(__int_as_float(m1.z), s1 + 1e-9f) : 0.f;
                float a2 = v2 ? __fdividef(__int_as_float(m2.z), s2 + 1e-9f) : 0.f;
                float a3 = v3 ? __fdividef(__int_as_float(m3.z), s3 + 1e-9f) : 0.f;

                float4 x0 = ((const float4*)x)[(size_t)m0.x * 32 + lane];
                float4 x1 = make_float4(0.f, 0.f, 0.f, 0.f);
                float4 x2 = make_float4(0.f, 0.f, 0.f, 0.f);
                float4 x3 = make_float4(0.f, 0.f, 0.f, 0.f);
                if (v1) x1 = ((const float4*)x)[(size_t)m1.x * 32 + lane];
                if (v2) x2 = ((const float4*)x)[(size_t)m2.x * 32 + lane];
                if (v3) x3 = ((const float4*)x)[(size_t)m3.x * 32 + lane];

                if (lane < 16) {
                    float4 e0 = __ldcs((const float4*)e_emb + (size_t)m0.y * 16 + lane);
                    float4 e1 = make_float4(0.f, 0.f, 0.f, 0.f);
                    float4 e2 = make_float4(0.f, 0.f, 0.f, 0.f);
                    float4 e3 = make_float4(0.f, 0.f, 0.f, 0.f);
                    if (v1) e1 = __ldcs((const float4*)e_emb + (size_t)m1.y * 16 + lane);
                    if (v2) e2 = __ldcs((const float4*)e_emb + (size_t)m2.y * 16 + lane);
                    if (v3) e3 = __ldcs((const float4*)e_emb + (size_t)m3.y * 16 + lane);
                    ua.x += a0 * e0.x + a1 * e1.x + a2 * e2.x + a3 * e3.x;
                    ua.y += a0 * e0.y + a1 * e1.y + a2 * e2.y + a3 * e3.y;
                    ua.z += a0 * e0.z + a1 * e1.z + a2 * e2.z + a3 * e3.z;
                    ua.w += a0 * e0.w + a1 * e1.w + a2 * e2.w + a3 * e3.w;
                }

                ya.x += a0 * x0.x + a1 * x1.x + a2 * x2.x + a3 * x3.x;
                ya.y += a0 * x0.y + a1 * x1.y + a2 * x2.y + a3 * x3.y;
                ya.z += a0 * x0.z + a1 * x1.z + a2 * x2.z + a3 * x3.z;
                ya.w += a0 * x0.w + a1 * x1.w + a2 * x2.w + a3 * x3.w;
                asum += a0 + a1 + a2 + a3;
            }
            *(float4*)(buf + li * NMS + 4 * lane) = ya;
            if (lane < 16)
                *(float4*)(buf + li * NMS + DD + 4 * lane) = ua;
            if (lane == 0) as[li] = asum;
        }
    }
    __syncthreads();

    // ---- Phase 2: register-staged in-place transpose -> yq[j][32] ----
    {
        int i = t & 31, g = t >> 5;
        float4 ry[8], ru[4];
        #pragma unroll
        for (int q = 0; q < 8; q++)
            ry[q] = *(const float4*)(buf + i * NMS + g * 32 + q * 4);
        #pragma unroll
        for (int q = 0; q < 4; q++)
            ru[q] = *(const float4*)(buf + i * NMS + DD + g * 16 + q * 4);
        __syncthreads();
        #pragma unroll
        for (int q = 0; q < 8; q++) {
            int j = g * 32 + q * 4;
            buf[(j + 0) * NPB + i] = ry[q].x;
            buf[(j + 1) * NPB + i] = ry[q].y;
            buf[(j + 2) * NPB + i] = ry[q].z;
            buf[(j + 3) * NPB + i] = ry[q].w;
        }
        #pragma unroll
        for (int q = 0; q < 4; q++) {
            int j = DD + g * 16 + q * 4;
            buf[(j + 0) * NPB + i] = ru[q].x;
            buf[(j + 1) * NPB + i] = ru[q].y;
            buf[(j + 2) * NPB + i] = ru[q].z;
            buf[(j + 3) * NPB + i] = ru[q].w;
        }
    }
    __syncthreads();

    // ---- Phase 3: epilogue — 2 cols/thread, node-half per warp-pair ----
    const float* yq = buf;
    int c = t & 63;
    int h = t >> 6;
    int ib = h * 16;
    unsigned long long acc0[8] = {0, 0, 0, 0, 0, 0, 0, 0};
    unsigned long long acc1[8] = {0, 0, 0, 0, 0, 0, 0, 0};

    #pragma unroll 4
    for (int j = 0; j < DD; j++) {
        unsigned long long w20 = pk2(Wv[j * DD + c]);
        unsigned long long w21 = pk2(Wv[j * DD + c + 64]);
        const ulonglong2* yr = (const ulonglong2*)(yq + j * NPB + ib);
        ulonglong2 p0 = yr[0], p1 = yr[1], p2 = yr[2], p3 = yr[3];
        ffma2(acc0[0], p0.x, w20); ffma2(acc0[1], p0.y, w20);
        ffma2(acc0[2], p1.x, w20); ffma2(acc0[3], p1.y, w20);
        ffma2(acc0[4], p2.x, w20); ffma2(acc0[5], p2.y, w20);
        ffma2(acc0[6], p3.x, w20); ffma2(acc0[7], p3.y, w20);
        ffma2(acc1[0], p0.x, w21); ffma2(acc1[1], p0.y, w21);
        ffma2(acc1[2], p1.x, w21); ffma2(acc1[3], p1.y, w21);
        ffma2(acc1[4], p2.x, w21); ffma2(acc1[5], p2.y, w21);
        ffma2(acc1[6], p3.x, w21); ffma2(acc1[7], p3.y, w21);
    }
    #pragma unroll 4
    for (int j = 0; j < DE; j++) {
        unsigned long long w20 = pk2(Wev[j * DD + c]);
        unsigned long long w21 = pk2(Wev[j * DD + c + 64]);
        const ulonglong2* yr = (const ulonglong2*)(yq + (DD + j) * NPB + ib);
        ulonglong2 p0 = yr[0], p1 = yr[1], p2 = yr[2], p3 = yr[3];
        ffma2(acc0[0], p0.x, w20); ffma2(acc0[1], p0.y, w20);
        ffma2(acc0[2], p1.x, w20); ffma2(acc0[3], p1.y, w20);
        ffma2(acc0[4], p2.x, w20); ffma2(acc0[5], p2.y, w20);
        ffma2(acc0[6], p3.x, w20); ffma2(acc0[7], p3.y, w20);
        ffma2(acc1[0], p0.x, w21); ffma2(acc1[1], p0.y, w21);
        ffma2(acc1[2], p1.x, w21); ffma2(acc1[3], p1.y, w21);
        ffma2(acc1[4], p2.x, w21); ffma2(acc1[5], p2.y, w21);
        ffma2(acc1[6], p3.x, w21); ffma2(acc1[7], p3.y, w21);
    }

    float bb0 = bv[c] + bev[c];
    float bb1 = bv[c + 64] + bev[c + 64];
    #pragma unroll
    for (int m = 0; m < 8; m++) {
        float lo0, hi0, lo1, hi1;
        asm("mov.b64 {%0, %1}, %2;" : "=f"(lo0), "=f"(hi0) : "l"(acc0[m]));
        asm("mov.b64 {%0, %1}, %2;" : "=f"(lo1), "=f"(hi1) : "l"(acc1[m]));
        int n = n0 + ib + 2 * m;
        float a_lo = as[ib + 2 * m + 0];
        float a_hi = as[ib + 2 * m + 1];
        out[(size_t)(n + 0) * DD + c]      = lo0 + a_lo * bb0;
        out[(size_t)(n + 1) * DD + c]      = hi0 + a_hi * bb0;
        out[(size_t)(n + 0) * DD + c + 64] = lo1 + a_lo * bb1;
        out[(size_t)(n + 1) * DD + c + 64] = hi1 + a_hi * bb1;
    }
}

// ---------------------------------------------------------------------------
extern "C" void kernel_launch(void* const* d_in, const int* in_sizes, int n_in,
                              void* d_out, int out_size) {
    const float* x     = (const float*)d_in[0];
    const int*   ei    = (const int*)d_in[1];
    const float* e_emb = (const float*)d_in[2];
    const int*   bi    = (const int*)d_in[3];

    int wb = 4;
    if (n_in >= 16 && in_sizes[4] <= 1) wb = 5;
    const float* Wq  = (const float*)d_in[wb + 0];
    const float* bq  = (const float*)d_in[wb + 1];
    const float* Wk  = (const float*)d_in[wb + 2];
    const float* bk  = (const float*)d_in[wb + 3];
    const float* Wv  = (const float*)d_in[wb + 4];
    const float* bv  = (const float*)d_in[wb + 5];
    const float* Wew = (const float*)d_in[wb + 6];
    const float* bew = (const float*)d_in[wb + 7];
    const float* Wev = (const float*)d_in[wb + 8];
    const float* bev = (const float*)d_in[wb + 9];
    const float* Wa  = (const float*)d_in[wb + 10];

    float* out = (float*)d_out;

    k_prep<<<2, 256>>>(Wq, Wk, Wew, bq, bk, bew, Wa);
    k_node<<<BN / 8, 256>>>(x);
    k_edge1<<<(EE * 4) / 128, 128>>>(ei, bi, e_emb);
    k_fused<<<BN / NPB, 128>>>(x, e_emb, Wv, bv, Wev, bev, out);
    (void)out_size;
}